// round 12
// baseline (speedup 1.0000x reference)
#include <cuda_runtime.h>
#include <cuda_bf16.h>
#include <cstdint>

// Problem dims (fixed)
#define BATCH  4
#define SEQ    2048
#define DMODEL 1024
#define NHEAD  16
#define HDIM   64
#define MROWS  (BATCH*SEQ)   // 8192

// ---------------------------------------------------------------------------
// Scratch (device-static: allocation-free per harness rules)
// ---------------------------------------------------------------------------
__device__ float g_y[(size_t)MROWS*DMODEL];
__device__ __nv_bfloat16 g_xb[(size_t)MROWS*DMODEL];
__device__ __nv_bfloat16 g_qkvb[(size_t)3*MROWS*DMODEL];
__device__ __nv_bfloat16 g_ob[(size_t)MROWS*DMODEL];
__device__ __nv_bfloat16 g_wqkv[(size_t)3*DMODEL*DMODEL];  // [3*N, K] transposed
__device__ __nv_bfloat16 g_wpb[(size_t)DMODEL*DMODEL];

// ---------------------------------------------------------------------------
// PTX helpers (base ISA only — sm_103 target has no tcgen05)
// ---------------------------------------------------------------------------
__device__ __forceinline__ uint32_t smem_u32(const void* p) {
    uint32_t a;
    asm("{ .reg .u64 t; cvta.to.shared.u64 t, %1; cvt.u32.u64 %0, t; }" : "=r"(a) : "l"(p));
    return a;
}
#define CP_ASYNC16(dst, src) \
    asm volatile("cp.async.cg.shared.global [%0], [%1], 16;" :: "r"(dst), "l"(src))
#define CP_COMMIT()   asm volatile("cp.async.commit_group;")
#define CP_WAIT(N)    asm volatile("cp.async.wait_group %0;" :: "n"(N))

__device__ __forceinline__ void ldmx4(uint32_t addr, uint32_t& r0, uint32_t& r1,
                                      uint32_t& r2, uint32_t& r3) {
    asm volatile("ldmatrix.sync.aligned.m8n8.x4.shared.b16 {%0,%1,%2,%3}, [%4];"
                 : "=r"(r0), "=r"(r1), "=r"(r2), "=r"(r3) : "r"(addr));
}
__device__ __forceinline__ void ldmx4t(uint32_t addr, uint32_t& r0, uint32_t& r1,
                                       uint32_t& r2, uint32_t& r3) {
    asm volatile("ldmatrix.sync.aligned.m8n8.x4.trans.shared.b16 {%0,%1,%2,%3}, [%4];"
                 : "=r"(r0), "=r"(r1), "=r"(r2), "=r"(r3) : "r"(addr));
}
__device__ __forceinline__ void mma_bf16(float c[4], uint32_t a0, uint32_t a1,
                                         uint32_t a2, uint32_t a3,
                                         uint32_t b0, uint32_t b1) {
    asm volatile("mma.sync.aligned.m16n8k16.row.col.f32.bf16.bf16.f32 "
                 "{%0,%1,%2,%3}, {%4,%5,%6,%7}, {%8,%9}, {%0,%1,%2,%3};"
                 : "+f"(c[0]), "+f"(c[1]), "+f"(c[2]), "+f"(c[3])
                 : "r"(a0), "r"(a1), "r"(a2), "r"(a3), "r"(b0), "r"(b1));
}
__device__ __forceinline__ float ex2(float x) {
    float y; asm("ex2.approx.ftz.f32 %0, %1;" : "=f"(y) : "f"(x)); return y;
}
__device__ __forceinline__ uint32_t pack_bf16(float a, float b) {
    __nv_bfloat162 v = __floats2bfloat162_rn(a, b);
    return *(uint32_t*)&v;
}

// ---------------------------------------------------------------------------
// bf16 mma.sync GEMM: C = A[M,K] @ Bt[N,K]^T, 128x128 tile, BK=32,
// 3-stage cp.async ring, ONE __syncthreads per K-iteration.
// MODE 0: bf16 out, N=3072 fused QKV (output split into 3 [MROWS,DMODEL]).
// MODE 1: fp32 out + bias + resid, N=1024.
// ---------------------------------------------------------------------------
#define BM  128
#define BN  128
#define BKK 32
#define STR 40
#define NITER (DMODEL / BKK)          // 32
#define STGB  (BM * STR * 2)          // 10240 B per operand per stage
#define GSTG  (2 * STGB)              // 20480 B per stage (A + B)
#define GSMEM (3 * GSTG)              // 61440 B

template<int MODE>
__global__ __launch_bounds__(256)
void gemm_mma(const __nv_bfloat16* __restrict__ A, const __nv_bfloat16* __restrict__ Bt,
              void* __restrict__ Cv, const float* __restrict__ bias,
              const float* __restrict__ resid)
{
    extern __shared__ char gsm[];
    const uint32_t sS = smem_u32(gsm);

    const int t    = threadIdx.x;
    const int lane = t & 31;
    const int warp = t >> 5;
    const int wm   = (warp >> 2) * 64;
    const int wn   = (warp & 3) * 32;
    const int bm   = blockIdx.y * BM;
    const int bn   = blockIdx.x * BN;

    const int lr = t >> 2;
    const int lc = (t & 3) * 8;

    const __nv_bfloat16* a0 = A  + (size_t)(bm + lr) * DMODEL + lc;
    const __nv_bfloat16* a1 = A  + (size_t)(bm + lr + 64) * DMODEL + lc;
    const __nv_bfloat16* b0 = Bt + (size_t)(bn + lr) * DMODEL + lc;
    const __nv_bfloat16* b1 = Bt + (size_t)(bn + lr + 64) * DMODEL + lc;

    const uint32_t dA0 = (uint32_t)(lr * STR + lc) * 2;
    const uint32_t dA1 = (uint32_t)((lr + 64) * STR + lc) * 2;

    float acc[4][4][4];
#pragma unroll
    for (int i = 0; i < 4; i++)
#pragma unroll
        for (int j = 0; j < 4; j++)
#pragma unroll
            for (int e = 0; e < 4; e++) acc[i][j][e] = 0.f;

    // prologue: stages 0,1
#pragma unroll
    for (int p = 0; p < 2; p++) {
        const uint32_t bo = sS + (uint32_t)p * GSTG;
        const int ko = p * BKK;
        CP_ASYNC16(bo + dA0, a0 + ko);
        CP_ASYNC16(bo + dA1, a1 + ko);
        CP_ASYNC16(bo + STGB + dA0, b0 + ko);
        CP_ASYNC16(bo + STGB + dA1, b1 + ko);
        CP_COMMIT();
    }

    const uint32_t aoff = (uint32_t)((wm + (lane & 15)) * STR + ((lane >> 4) << 3)) * 2;
    const uint32_t boff = STGB + (uint32_t)((wn + ((lane >> 4) << 3) + (lane & 7)) * STR
                                            + (((lane >> 3) & 1) << 3)) * 2;

    int buf = 0, nbuf = 2;
    for (int it = 0; it < NITER; it++) {
        if (it + 1 < NITER) { CP_WAIT(1); } else { CP_WAIT(0); }
        __syncthreads();
        if (it + 2 < NITER) {
            const uint32_t bo = sS + (uint32_t)nbuf * GSTG;
            const int ko = (it + 2) * BKK;
            CP_ASYNC16(bo + dA0, a0 + ko);
            CP_ASYNC16(bo + dA1, a1 + ko);
            CP_ASYNC16(bo + STGB + dA0, b0 + ko);
            CP_ASYNC16(bo + STGB + dA1, b1 + ko);
            CP_COMMIT();
            nbuf = (nbuf == 2) ? 0 : nbuf + 1;
        }

        const uint32_t base = sS + (uint32_t)buf * GSTG;
        buf = (buf == 2) ? 0 : buf + 1;
#pragma unroll
        for (int kh = 0; kh < 2; kh++) {
            uint32_t a[4][4], bfr[4][2];
#pragma unroll
            for (int mi = 0; mi < 4; mi++) {
                uint32_t addr = base + aoff + (uint32_t)(mi * 16 * STR + kh * 16) * 2;
                ldmx4(addr, a[mi][0], a[mi][1], a[mi][2], a[mi][3]);
            }
#pragma unroll
            for (int j = 0; j < 2; j++) {
                uint32_t addr = base + boff + (uint32_t)(j * 16 * STR + kh * 16) * 2;
                uint32_t r0, r1, r2, r3;
                ldmx4(addr, r0, r1, r2, r3);
                bfr[j*2][0] = r0; bfr[j*2][1] = r1;
                bfr[j*2+1][0] = r2; bfr[j*2+1][1] = r3;
            }
#pragma unroll
            for (int mi = 0; mi < 4; mi++)
#pragma unroll
                for (int ni = 0; ni < 4; ni++)
                    mma_bf16(acc[mi][ni], a[mi][0], a[mi][1], a[mi][2], a[mi][3],
                             bfr[ni][0], bfr[ni][1]);
        }
    }

    // epilogue
    const int r0 = bm + wm + (lane >> 2);
#pragma unroll
    for (int mi = 0; mi < 4; mi++) {
#pragma unroll
        for (int ni = 0; ni < 4; ni++) {
            const int row = r0 + mi * 16;
            if constexpr (MODE == 0) {
                __nv_bfloat16* Cb = (__nv_bfloat16*)Cv
                    + (size_t)(bn >> 10) * MROWS * DMODEL;
                const int col = (bn & 1023) + wn + (lane & 3) * 2 + ni * 8;
                *(__nv_bfloat162*)(Cb + (size_t)row * DMODEL + col) =
                    __floats2bfloat162_rn(acc[mi][ni][0], acc[mi][ni][1]);
                *(__nv_bfloat162*)(Cb + (size_t)(row + 8) * DMODEL + col) =
                    __floats2bfloat162_rn(acc[mi][ni][2], acc[mi][ni][3]);
            } else {
                float* Cf = (float*)Cv;
                const int col = bn + wn + (lane & 3) * 2 + ni * 8;
                float2 v0 = make_float2(acc[mi][ni][0], acc[mi][ni][1]);
                float2 v1 = make_float2(acc[mi][ni][2], acc[mi][ni][3]);
                const float2 bb = *(const float2*)(bias + col);
                const float2 x0 = *(const float2*)(resid + (size_t)row * DMODEL + col);
                const float2 x1 = *(const float2*)(resid + (size_t)(row + 8) * DMODEL + col);
                v0.x += bb.x + x0.x; v0.y += bb.y + x0.y;
                v1.x += bb.x + x1.x; v1.y += bb.y + x1.y;
                *(float2*)(Cf + (size_t)row * DMODEL + col)       = v0;
                *(float2*)(Cf + (size_t)(row + 8) * DMODEL + col) = v1;
            }
        }
    }
}

// ---------------------------------------------------------------------------
// Flash attention on mma.sync (bf16 in/out, fp32 accum), fixed-max softmax.
// 128 threads, 4 warps; each warp owns 32 Q rows (two m16 slabs).
// __launch_bounds__(128, 3): cap regs at 170 so 3 CTAs fit per SM
// (21.7K regs/CTA x3 = 65.2K <= 64K regfile; smem 73.7KB x3 = 221KB <= 228KB).
// BQ=128, BKV=64; 3-stage KV ring, one __syncthreads per iteration.
// ---------------------------------------------------------------------------
#define ATQ   128
#define ATKV  64
#define ASTR  72
#define AQBYTES  (ATQ * ASTR * 2)          // 18432
#define AKVB     (ATKV * ASTR * 2)         // 9216 (per tensor)
#define ASTGB    (2 * AKVB)                // 18432 (K + V per stage)
#define ASMEM    (AQBYTES + 3 * ASTGB)     // 73728
#define CEXP  0.180336880f                 // 0.125 * log2(e)
#define NKV   (SEQ / ATKV)                 // 32

__global__ __launch_bounds__(128, 3)
void attn_mma(const __nv_bfloat16* __restrict__ Q, const __nv_bfloat16* __restrict__ K,
              const __nv_bfloat16* __restrict__ V, __nv_bfloat16* __restrict__ O)
{
    extern __shared__ char smattn[];
    const uint32_t sQ = smem_u32(smattn);
    const uint32_t sKV = sQ + AQBYTES;     // stage s: K at s*ASTGB, V at +AKVB

    const int t = threadIdx.x, lane = t & 31, warp = t >> 5;   // warp 0..3
    const int b = blockIdx.z, h = blockIdx.y;
    const int q0 = blockIdx.x * ATQ;
    const size_t base = (size_t)b * SEQ * DMODEL + (size_t)h * HDIM;

    // prologue: Q (1 group), KV stages 0,1 (1 group each). 128 threads.
#pragma unroll
    for (int i = 0; i < 8; i++) {
        int idx = t + i * 128, row = idx >> 3, ch = idx & 7;
        CP_ASYNC16(sQ + (uint32_t)(row * ASTR + ch * 8) * 2,
                   Q + base + (size_t)(q0 + row) * DMODEL + ch * 8);
    }
    CP_COMMIT();
#pragma unroll
    for (int p = 0; p < 2; p++) {
        const uint32_t bo = sKV + (uint32_t)p * ASTGB;
        const size_t kvb = base + (size_t)(p * ATKV) * DMODEL;
#pragma unroll
        for (int i = 0; i < 4; i++) {
            int idx = t + i * 128, row = idx >> 3, ch = idx & 7;
            CP_ASYNC16(bo + (uint32_t)(row * ASTR + ch * 8) * 2,
                       K + kvb + (size_t)row * DMODEL + ch * 8);
            CP_ASYNC16(bo + AKVB + (uint32_t)(row * ASTR + ch * 8) * 2,
                       V + kvb + (size_t)row * DMODEL + ch * 8);
        }
        CP_COMMIT();
    }

    CP_WAIT(2);            // Q done (KV stages may be pending)
    __syncthreads();

    // Q fragments for both slabs, resident for the whole KV loop
    uint32_t qa0[4][4], qa1[4][4];
    {
        const uint32_t aq0 = (uint32_t)((warp * 32 + (lane & 15)) * ASTR + ((lane >> 4) << 3));
        const uint32_t aq1 = (uint32_t)((warp * 32 + 16 + (lane & 15)) * ASTR + ((lane >> 4) << 3));
#pragma unroll
        for (int kh = 0; kh < 4; kh++) {
            ldmx4(sQ + (aq0 + kh * 16) * 2, qa0[kh][0], qa0[kh][1], qa0[kh][2], qa0[kh][3]);
            ldmx4(sQ + (aq1 + kh * 16) * 2, qa1[kh][0], qa1[kh][1], qa1[kh][2], qa1[kh][3]);
        }
    }

    float oacc0[8][4], oacc1[8][4];
#pragma unroll
    for (int j = 0; j < 8; j++)
#pragma unroll
        for (int e = 0; e < 4; e++) { oacc0[j][e] = 0.f; oacc1[j][e] = 0.f; }
    float l0a = 0.f, l0b = 0.f, l1a = 0.f, l1b = 0.f;

    const uint32_t koff = (uint32_t)((((lane >> 4) << 3) + (lane & 7)) * ASTR
                                     + (((lane >> 3) & 1) << 3));
    const uint32_t voff = (uint32_t)((lane & 15) * ASTR + ((lane >> 4) << 3));

    int buf = 0, nbuf = 2;
    for (int it = 0; it < NKV; it++) {
        if (it + 1 < NKV) { CP_WAIT(1); } else { CP_WAIT(0); }
        __syncthreads();
        if (it + 2 < NKV) {
            const uint32_t bo = sKV + (uint32_t)nbuf * ASTGB;
            const size_t kvb = base + (size_t)((it + 2) * ATKV) * DMODEL;
#pragma unroll
            for (int i = 0; i < 4; i++) {
                int idx = t + i * 128, row = idx >> 3, ch = idx & 7;
                CP_ASYNC16(bo + (uint32_t)(row * ASTR + ch * 8) * 2,
                           K + kvb + (size_t)row * DMODEL + ch * 8);
                CP_ASYNC16(bo + AKVB + (uint32_t)(row * ASTR + ch * 8) * 2,
                           V + kvb + (size_t)row * DMODEL + ch * 8);
            }
            CP_COMMIT();
            nbuf = (nbuf == 2) ? 0 : nbuf + 1;
        }

        const uint32_t kb = sKV + (uint32_t)buf * ASTGB;
        const uint32_t vb = kb + AKVB;
        buf = (buf == 2) ? 0 : buf + 1;

        uint32_t pa0[4][4], pa1[4][4];
        // S = Q @ K^T in two n-halves (keys [0,32) then [32,64)) to cap regs
#pragma unroll
        for (int half = 0; half < 2; half++) {
            float s0[4][4], s1[4][4];
#pragma unroll
            for (int j = 0; j < 4; j++)
#pragma unroll
                for (int e = 0; e < 4; e++) { s0[j][e] = 0.f; s1[j][e] = 0.f; }
#pragma unroll
            for (int kh = 0; kh < 4; kh++) {
#pragma unroll
                for (int j2l = 0; j2l < 2; j2l++) {
                    const int j2 = half * 2 + j2l;
                    uint32_t r0, r1, r2, r3;
                    ldmx4(kb + (koff + (uint32_t)(j2 * 16 * ASTR + kh * 16)) * 2,
                          r0, r1, r2, r3);
                    mma_bf16(s0[j2l*2],   qa0[kh][0], qa0[kh][1], qa0[kh][2], qa0[kh][3], r0, r1);
                    mma_bf16(s0[j2l*2+1], qa0[kh][0], qa0[kh][1], qa0[kh][2], qa0[kh][3], r2, r3);
                    mma_bf16(s1[j2l*2],   qa1[kh][0], qa1[kh][1], qa1[kh][2], qa1[kh][3], r0, r1);
                    mma_bf16(s1[j2l*2+1], qa1[kh][0], qa1[kh][1], qa1[kh][2], qa1[kh][3], r2, r3);
                }
            }
            // fixed-max softmax: p = 2^(s*CEXP)
#pragma unroll
            for (int j2l = 0; j2l < 2; j2l++) {
#pragma unroll
                for (int u = 0; u < 2; u++) {
                    const int j = j2l * 2 + u;
                    float p00 = ex2(s0[j][0] * CEXP);
                    float p01 = ex2(s0[j][1] * CEXP);
                    float p02 = ex2(s0[j][2] * CEXP);
                    float p03 = ex2(s0[j][3] * CEXP);
                    l0a += p00 + p01; l0b += p02 + p03;
                    pa0[half*2 + j2l][u*2]     = pack_bf16(p00, p01);
                    pa0[half*2 + j2l][u*2 + 1] = pack_bf16(p02, p03);
                    float p10 = ex2(s1[j][0] * CEXP);
                    float p11 = ex2(s1[j][1] * CEXP);
                    float p12 = ex2(s1[j][2] * CEXP);
                    float p13 = ex2(s1[j][3] * CEXP);
                    l1a += p10 + p11; l1b += p12 + p13;
                    pa1[half*2 + j2l][u*2]     = pack_bf16(p10, p11);
                    pa1[half*2 + j2l][u*2 + 1] = pack_bf16(p12, p13);
                }
            }
        }

        // O += P @ V (un-normalized); each V fragment feeds both slabs
#pragma unroll
        for (int kk = 0; kk < 4; kk++) {
#pragma unroll
            for (int j2 = 0; j2 < 4; j2++) {
                uint32_t r0, r1, r2, r3;
                ldmx4t(vb + (voff + (uint32_t)(kk * 16 * ASTR + j2 * 16)) * 2, r0, r1, r2, r3);
                mma_bf16(oacc0[j2*2],   pa0[kk][0], pa0[kk][1], pa0[kk][2], pa0[kk][3], r0, r1);
                mma_bf16(oacc0[j2*2+1], pa0[kk][0], pa0[kk][1], pa0[kk][2], pa0[kk][3], r2, r3);
                mma_bf16(oacc1[j2*2],   pa1[kk][0], pa1[kk][1], pa1[kk][2], pa1[kk][3], r0, r1);
                mma_bf16(oacc1[j2*2+1], pa1[kk][0], pa1[kk][1], pa1[kk][2], pa1[kk][3], r2, r3);
            }
        }
    }

    l0a += __shfl_xor_sync(0xffffffffu, l0a, 1);
    l0a += __shfl_xor_sync(0xffffffffu, l0a, 2);
    l0b += __shfl_xor_sync(0xffffffffu, l0b, 1);
    l0b += __shfl_xor_sync(0xffffffffu, l0b, 2);
    l1a += __shfl_xor_sync(0xffffffffu, l1a, 1);
    l1a += __shfl_xor_sync(0xffffffffu, l1a, 2);
    l1b += __shfl_xor_sync(0xffffffffu, l1b, 1);
    l1b += __shfl_xor_sync(0xffffffffu, l1b, 2);
    const float i0a = 1.f / l0a, i0b = 1.f / l0b;
    const float i1a = 1.f / l1a, i1b = 1.f / l1b;

    const int r0r = warp * 32 + (lane >> 2);
    __nv_bfloat16* o0 = O + (size_t)(b * SEQ + q0 + r0r) * DMODEL + h * HDIM + (lane & 3) * 2;
    __nv_bfloat16* o1 = o0 + (size_t)8 * DMODEL;
    __nv_bfloat16* o2 = o0 + (size_t)16 * DMODEL;
    __nv_bfloat16* o3 = o0 + (size_t)24 * DMODEL;
#pragma unroll
    for (int jn = 0; jn < 8; jn++) {
        *(__nv_bfloat162*)(o0 + jn * 8) =
            __floats2bfloat162_rn(oacc0[jn][0] * i0a, oacc0[jn][1] * i0a);
        *(__nv_bfloat162*)(o1 + jn * 8) =
            __floats2bfloat162_rn(oacc0[jn][2] * i0b, oacc0[jn][3] * i0b);
        *(__nv_bfloat162*)(o2 + jn * 8) =
            __floats2bfloat162_rn(oacc1[jn][0] * i1a, oacc1[jn][1] * i1a);
        *(__nv_bfloat162*)(o3 + jn * 8) =
            __floats2bfloat162_rn(oacc1[jn][2] * i1b, oacc1[jn][3] * i1b);
    }
}

// ---------------------------------------------------------------------------
// fp32 -> bf16 cast (elementwise, vectorized)
// ---------------------------------------------------------------------------
__global__ __launch_bounds__(256)
void cast_bf16(const float* __restrict__ in, __nv_bfloat16* __restrict__ out, int n4)
{
    int i = blockIdx.x * blockDim.x + threadIdx.x;
    if (i >= n4) return;
    float4 v = *(const float4*)(in + (size_t)i * 4);
    *(__nv_bfloat162*)(out + (size_t)i * 4)     = __floats2bfloat162_rn(v.x, v.y);
    *(__nv_bfloat162*)(out + (size_t)i * 4 + 2) = __floats2bfloat162_rn(v.z, v.w);
}

// ---------------------------------------------------------------------------
// Transpose + cast all 4 weights: in[K,N] fp32 -> out[N,K] bf16 (z selects).
// ---------------------------------------------------------------------------
__global__ __launch_bounds__(256)
void transpose_cast4(const float* __restrict__ w0, const float* __restrict__ w1,
                     const float* __restrict__ w2, const float* __restrict__ w3,
                     __nv_bfloat16* __restrict__ oqkv, __nv_bfloat16* __restrict__ op)
{
    const int z = blockIdx.z;
    const float* in  = (z == 0) ? w0 : (z == 1) ? w1 : (z == 2) ? w2 : w3;
    __nv_bfloat16* out = (z < 3) ? (oqkv + (size_t)z * DMODEL * DMODEL) : op;
    __shared__ float tile[32][33];
    const int n0 = blockIdx.x * 32;
    const int k0 = blockIdx.y * 32;
    const int tx = threadIdx.x & 31;
    const int ty = threadIdx.x >> 5;   // 0..7
#pragma unroll
    for (int i = 0; i < 32; i += 8)
        tile[ty + i][tx] = in[(size_t)(k0 + ty + i) * DMODEL + n0 + tx];
    __syncthreads();
#pragma unroll
    for (int i = 0; i < 32; i += 8)
        out[(size_t)(n0 + ty + i) * DMODEL + k0 + tx] = __float2bfloat16(tile[tx][ty + i]);
}

// ---------------------------------------------------------------------------
// LayerNorm: one block per row (1024 elems), 256 threads, eps = 1e-6
// ---------------------------------------------------------------------------
__global__ __launch_bounds__(256)
void ln_kernel(const float* __restrict__ Y, const float* __restrict__ gamma,
               const float* __restrict__ beta, float* __restrict__ out)
{
    const int row = blockIdx.x;
    const int t = threadIdx.x;
    const float* y = Y + (size_t)row * DMODEL;

    float4 v = *(const float4*)(y + t * 4);
    float s  = v.x + v.y + v.z + v.w;
    float ss = v.x*v.x + v.y*v.y + v.z*v.z + v.w*v.w;

    __shared__ float rs[8], rss[8];
    int lane = t & 31, wid = t >> 5;
#pragma unroll
    for (int o = 16; o > 0; o >>= 1) {
        s  += __shfl_xor_sync(0xffffffffu, s,  o);
        ss += __shfl_xor_sync(0xffffffffu, ss, o);
    }
    if (lane == 0) { rs[wid] = s; rss[wid] = ss; }
    __syncthreads();
    if (wid == 0) {
        s  = (lane < 8) ? rs[lane]  : 0.f;
        ss = (lane < 8) ? rss[lane] : 0.f;
#pragma unroll
        for (int o = 4; o > 0; o >>= 1) {
            s  += __shfl_xor_sync(0xffffffffu, s,  o);
            ss += __shfl_xor_sync(0xffffffffu, ss, o);
        }
        if (lane == 0) { rs[0] = s; rss[0] = ss; }
    }
    __syncthreads();

    float mean = rs[0] * (1.f / DMODEL);
    float var  = rss[0] * (1.f / DMODEL) - mean * mean;
    float rstd = rsqrtf(var + 1e-6f);

    float4 g  = *(const float4*)(gamma + t * 4);
    float4 be = *(const float4*)(beta  + t * 4);
    float4 r;
    r.x = (v.x - mean) * rstd * g.x + be.x;
    r.y = (v.y - mean) * rstd * g.y + be.y;
    r.z = (v.z - mean) * rstd * g.z + be.z;
    r.w = (v.w - mean) * rstd * g.w + be.w;
    *(float4*)(out + (size_t)row * DMODEL + t * 4) = r;
}

// ---------------------------------------------------------------------------
// Launch
// ---------------------------------------------------------------------------
extern "C" void kernel_launch(void* const* d_in, const int* in_sizes, int n_in,
                              void* d_out, int out_size)
{
    const float* x      = (const float*)d_in[0];
    const float* w_q    = (const float*)d_in[1];
    const float* w_k    = (const float*)d_in[2];
    const float* w_v    = (const float*)d_in[3];
    const float* w_proj = (const float*)d_in[4];
    const float* b_proj = (const float*)d_in[5];
    const float* gamma  = (const float*)d_in[6];
    const float* beta   = (const float*)d_in[7];
    float* out = (float*)d_out;

    float* y;
    __nv_bfloat16 *xb, *qkvb, *ob, *wqkv, *wpb;
    cudaGetSymbolAddress((void**)&y,    g_y);
    cudaGetSymbolAddress((void**)&xb,   g_xb);
    cudaGetSymbolAddress((void**)&qkvb, g_qkvb);
    cudaGetSymbolAddress((void**)&ob,   g_ob);
    cudaGetSymbolAddress((void**)&wqkv, g_wqkv);
    cudaGetSymbolAddress((void**)&wpb,  g_wpb);

    cudaFuncSetAttribute(gemm_mma<0>, cudaFuncAttributeMaxDynamicSharedMemorySize, GSMEM);
    cudaFuncSetAttribute(gemm_mma<1>, cudaFuncAttributeMaxDynamicSharedMemorySize, GSMEM);
    cudaFuncSetAttribute(attn_mma, cudaFuncAttributeMaxDynamicSharedMemorySize, ASMEM);

    // Casts / weight transposes
    const int n4 = MROWS * DMODEL / 4;
    cast_bf16<<<(n4 + 255) / 256, 256>>>(x, xb, n4);
    dim3 tg(DMODEL / 32, DMODEL / 32, 4);
    transpose_cast4<<<tg, 256>>>(w_q, w_k, w_v, w_proj, wqkv, wpb);

    // Fused QKV projection (bf16 out, split into q/k/v regions)
    dim3 gq(3 * DMODEL / BN, MROWS / BM);   // (24, 64)
    gemm_mma<0><<<gq, 256, GSMEM>>>(xb, wqkv, qkvb, nullptr, nullptr);

    // Flash attention on tensor cores (fixed-max softmax, 2 slabs/warp, 3 CTA/SM)
    dim3 ga(SEQ / ATQ, NHEAD, BATCH);       // (16, 16, 4)
    attn_mma<<<ga, 128, ASMEM>>>(qkvb, qkvb + (size_t)MROWS * DMODEL,
                                 qkvb + (size_t)2 * MROWS * DMODEL, ob);

    // proj + bias + residual (fp32 out)
    dim3 gp(DMODEL / BN, MROWS / BM);       // (8, 64)
    gemm_mma<1><<<gp, 256, GSMEM>>>(ob, wpb, y, b_proj, x);

    ln_kernel<<<MROWS, 256>>>(y, gamma, beta, out);
}

// round 13
// speedup vs baseline: 1.4894x; 1.4894x over previous
#include <cuda_runtime.h>
#include <cuda_bf16.h>
#include <cstdint>

// Problem dims (fixed)
#define BATCH  4
#define SEQ    2048
#define DMODEL 1024
#define NHEAD  16
#define HDIM   64
#define MROWS  (BATCH*SEQ)   // 8192

// ---------------------------------------------------------------------------
// Scratch (device-static: allocation-free per harness rules)
// ---------------------------------------------------------------------------
__device__ float g_y[(size_t)MROWS*DMODEL];
__device__ __nv_bfloat16 g_xb[(size_t)MROWS*DMODEL];
__device__ __nv_bfloat16 g_qkvb[(size_t)3*MROWS*DMODEL];
__device__ __nv_bfloat16 g_ob[(size_t)MROWS*DMODEL];
__device__ __nv_bfloat16 g_wqkv[(size_t)3*DMODEL*DMODEL];  // [3*N, K] transposed
__device__ __nv_bfloat16 g_wpb[(size_t)DMODEL*DMODEL];

// ---------------------------------------------------------------------------
// PTX helpers (base ISA only — sm_103 target has no tcgen05)
// ---------------------------------------------------------------------------
__device__ __forceinline__ uint32_t smem_u32(const void* p) {
    uint32_t a;
    asm("{ .reg .u64 t; cvta.to.shared.u64 t, %1; cvt.u32.u64 %0, t; }" : "=r"(a) : "l"(p));
    return a;
}
#define CP_ASYNC16(dst, src) \
    asm volatile("cp.async.cg.shared.global [%0], [%1], 16;" :: "r"(dst), "l"(src))
#define CP_COMMIT()   asm volatile("cp.async.commit_group;")
#define CP_WAIT(N)    asm volatile("cp.async.wait_group %0;" :: "n"(N))

__device__ __forceinline__ void ldmx4(uint32_t addr, uint32_t& r0, uint32_t& r1,
                                      uint32_t& r2, uint32_t& r3) {
    asm volatile("ldmatrix.sync.aligned.m8n8.x4.shared.b16 {%0,%1,%2,%3}, [%4];"
                 : "=r"(r0), "=r"(r1), "=r"(r2), "=r"(r3) : "r"(addr));
}
__device__ __forceinline__ void ldmx4t(uint32_t addr, uint32_t& r0, uint32_t& r1,
                                       uint32_t& r2, uint32_t& r3) {
    asm volatile("ldmatrix.sync.aligned.m8n8.x4.trans.shared.b16 {%0,%1,%2,%3}, [%4];"
                 : "=r"(r0), "=r"(r1), "=r"(r2), "=r"(r3) : "r"(addr));
}
__device__ __forceinline__ void mma_bf16(float c[4], uint32_t a0, uint32_t a1,
                                         uint32_t a2, uint32_t a3,
                                         uint32_t b0, uint32_t b1) {
    asm volatile("mma.sync.aligned.m16n8k16.row.col.f32.bf16.bf16.f32 "
                 "{%0,%1,%2,%3}, {%4,%5,%6,%7}, {%8,%9}, {%0,%1,%2,%3};"
                 : "+f"(c[0]), "+f"(c[1]), "+f"(c[2]), "+f"(c[3])
                 : "r"(a0), "r"(a1), "r"(a2), "r"(a3), "r"(b0), "r"(b1));
}
__device__ __forceinline__ float ex2(float x) {
    float y; asm("ex2.approx.ftz.f32 %0, %1;" : "=f"(y) : "f"(x)); return y;
}
__device__ __forceinline__ uint32_t pack_bf16(float a, float b) {
    __nv_bfloat162 v = __floats2bfloat162_rn(a, b);
    return *(uint32_t*)&v;
}

// ---------------------------------------------------------------------------
// bf16 mma.sync GEMM: C = A[M,K] @ Bt[N,K]^T, 128x128 tile, BK=32,
// 3-stage cp.async ring, ONE __syncthreads per K-iteration.
// MODE 0: bf16 out, N=3072 fused QKV (output split into 3 [MROWS,DMODEL]).
// MODE 1: fp32 out + bias + resid, N=1024.
// ---------------------------------------------------------------------------
#define BM  128
#define BN  128
#define BKK 32
#define STR 40
#define NITER (DMODEL / BKK)          // 32
#define STGB  (BM * STR * 2)          // 10240 B per operand per stage
#define GSTG  (2 * STGB)              // 20480 B per stage (A + B)
#define GSMEM (3 * GSTG)              // 61440 B

template<int MODE>
__global__ __launch_bounds__(256)
void gemm_mma(const __nv_bfloat16* __restrict__ A, const __nv_bfloat16* __restrict__ Bt,
              void* __restrict__ Cv, const float* __restrict__ bias,
              const float* __restrict__ resid)
{
    extern __shared__ char gsm[];
    const uint32_t sS = smem_u32(gsm);

    const int t    = threadIdx.x;
    const int lane = t & 31;
    const int warp = t >> 5;
    const int wm   = (warp >> 2) * 64;
    const int wn   = (warp & 3) * 32;
    const int bm   = blockIdx.y * BM;
    const int bn   = blockIdx.x * BN;

    const int lr = t >> 2;
    const int lc = (t & 3) * 8;

    const __nv_bfloat16* a0 = A  + (size_t)(bm + lr) * DMODEL + lc;
    const __nv_bfloat16* a1 = A  + (size_t)(bm + lr + 64) * DMODEL + lc;
    const __nv_bfloat16* b0 = Bt + (size_t)(bn + lr) * DMODEL + lc;
    const __nv_bfloat16* b1 = Bt + (size_t)(bn + lr + 64) * DMODEL + lc;

    const uint32_t dA0 = (uint32_t)(lr * STR + lc) * 2;
    const uint32_t dA1 = (uint32_t)((lr + 64) * STR + lc) * 2;

    float acc[4][4][4];
#pragma unroll
    for (int i = 0; i < 4; i++)
#pragma unroll
        for (int j = 0; j < 4; j++)
#pragma unroll
            for (int e = 0; e < 4; e++) acc[i][j][e] = 0.f;

    // prologue: stages 0,1
#pragma unroll
    for (int p = 0; p < 2; p++) {
        const uint32_t bo = sS + (uint32_t)p * GSTG;
        const int ko = p * BKK;
        CP_ASYNC16(bo + dA0, a0 + ko);
        CP_ASYNC16(bo + dA1, a1 + ko);
        CP_ASYNC16(bo + STGB + dA0, b0 + ko);
        CP_ASYNC16(bo + STGB + dA1, b1 + ko);
        CP_COMMIT();
    }

    const uint32_t aoff = (uint32_t)((wm + (lane & 15)) * STR + ((lane >> 4) << 3)) * 2;
    const uint32_t boff = STGB + (uint32_t)((wn + ((lane >> 4) << 3) + (lane & 7)) * STR
                                            + (((lane >> 3) & 1) << 3)) * 2;

    int buf = 0, nbuf = 2;
    for (int it = 0; it < NITER; it++) {
        if (it + 1 < NITER) { CP_WAIT(1); } else { CP_WAIT(0); }
        __syncthreads();
        if (it + 2 < NITER) {
            const uint32_t bo = sS + (uint32_t)nbuf * GSTG;
            const int ko = (it + 2) * BKK;
            CP_ASYNC16(bo + dA0, a0 + ko);
            CP_ASYNC16(bo + dA1, a1 + ko);
            CP_ASYNC16(bo + STGB + dA0, b0 + ko);
            CP_ASYNC16(bo + STGB + dA1, b1 + ko);
            CP_COMMIT();
            nbuf = (nbuf == 2) ? 0 : nbuf + 1;
        }

        const uint32_t base = sS + (uint32_t)buf * GSTG;
        buf = (buf == 2) ? 0 : buf + 1;
#pragma unroll
        for (int kh = 0; kh < 2; kh++) {
            uint32_t a[4][4], bfr[4][2];
#pragma unroll
            for (int mi = 0; mi < 4; mi++) {
                uint32_t addr = base + aoff + (uint32_t)(mi * 16 * STR + kh * 16) * 2;
                ldmx4(addr, a[mi][0], a[mi][1], a[mi][2], a[mi][3]);
            }
#pragma unroll
            for (int j = 0; j < 2; j++) {
                uint32_t addr = base + boff + (uint32_t)(j * 16 * STR + kh * 16) * 2;
                uint32_t r0, r1, r2, r3;
                ldmx4(addr, r0, r1, r2, r3);
                bfr[j*2][0] = r0; bfr[j*2][1] = r1;
                bfr[j*2+1][0] = r2; bfr[j*2+1][1] = r3;
            }
#pragma unroll
            for (int mi = 0; mi < 4; mi++)
#pragma unroll
                for (int ni = 0; ni < 4; ni++)
                    mma_bf16(acc[mi][ni], a[mi][0], a[mi][1], a[mi][2], a[mi][3],
                             bfr[ni][0], bfr[ni][1]);
        }
    }

    // epilogue
    const int r0 = bm + wm + (lane >> 2);
#pragma unroll
    for (int mi = 0; mi < 4; mi++) {
#pragma unroll
        for (int ni = 0; ni < 4; ni++) {
            const int row = r0 + mi * 16;
            if constexpr (MODE == 0) {
                __nv_bfloat16* Cb = (__nv_bfloat16*)Cv
                    + (size_t)(bn >> 10) * MROWS * DMODEL;
                const int col = (bn & 1023) + wn + (lane & 3) * 2 + ni * 8;
                *(__nv_bfloat162*)(Cb + (size_t)row * DMODEL + col) =
                    __floats2bfloat162_rn(acc[mi][ni][0], acc[mi][ni][1]);
                *(__nv_bfloat162*)(Cb + (size_t)(row + 8) * DMODEL + col) =
                    __floats2bfloat162_rn(acc[mi][ni][2], acc[mi][ni][3]);
            } else {
                float* Cf = (float*)Cv;
                const int col = bn + wn + (lane & 3) * 2 + ni * 8;
                float2 v0 = make_float2(acc[mi][ni][0], acc[mi][ni][1]);
                float2 v1 = make_float2(acc[mi][ni][2], acc[mi][ni][3]);
                const float2 bb = *(const float2*)(bias + col);
                const float2 x0 = *(const float2*)(resid + (size_t)row * DMODEL + col);
                const float2 x1 = *(const float2*)(resid + (size_t)(row + 8) * DMODEL + col);
                v0.x += bb.x + x0.x; v0.y += bb.y + x0.y;
                v1.x += bb.x + x1.x; v1.y += bb.y + x1.y;
                *(float2*)(Cf + (size_t)row * DMODEL + col)       = v0;
                *(float2*)(Cf + (size_t)(row + 8) * DMODEL + col) = v1;
            }
        }
    }
}

// ---------------------------------------------------------------------------
// Flash attention on mma.sync (bf16 in/out, fp32 accum), fixed-max softmax.
// 128 threads, 4 warps; each warp owns 32 Q rows (two m16 slabs).
// Fused half-pipeline: for each 32-key half, S-MMA -> exp -> PV-MMA before
// touching the next half. Cuts live P fragments from [4][4] to [2][4] per
// slab (structurally lower regs -> natural 3 CTA/SM, no launch-bounds cap).
// BQ=128, BKV=64; 3-stage KV ring, one __syncthreads per iteration.
// ---------------------------------------------------------------------------
#define ATQ   128
#define ATKV  64
#define ASTR  72
#define AQBYTES  (ATQ * ASTR * 2)          // 18432
#define AKVB     (ATKV * ASTR * 2)         // 9216 (per tensor)
#define ASTGB    (2 * AKVB)                // 18432 (K + V per stage)
#define ASMEM    (AQBYTES + 3 * ASTGB)     // 73728
#define CEXP  0.180336880f                 // 0.125 * log2(e)
#define NKV   (SEQ / ATKV)                 // 32

__global__ __launch_bounds__(128)
void attn_mma(const __nv_bfloat16* __restrict__ Q, const __nv_bfloat16* __restrict__ K,
              const __nv_bfloat16* __restrict__ V, __nv_bfloat16* __restrict__ O)
{
    extern __shared__ char smattn[];
    const uint32_t sQ = smem_u32(smattn);
    const uint32_t sKV = sQ + AQBYTES;     // stage s: K at s*ASTGB, V at +AKVB

    const int t = threadIdx.x, lane = t & 31, warp = t >> 5;   // warp 0..3
    const int b = blockIdx.z, h = blockIdx.y;
    const int q0 = blockIdx.x * ATQ;
    const size_t base = (size_t)b * SEQ * DMODEL + (size_t)h * HDIM;

    // prologue: Q (1 group), KV stages 0,1 (1 group each). 128 threads.
#pragma unroll
    for (int i = 0; i < 8; i++) {
        int idx = t + i * 128, row = idx >> 3, ch = idx & 7;
        CP_ASYNC16(sQ + (uint32_t)(row * ASTR + ch * 8) * 2,
                   Q + base + (size_t)(q0 + row) * DMODEL + ch * 8);
    }
    CP_COMMIT();
#pragma unroll
    for (int p = 0; p < 2; p++) {
        const uint32_t bo = sKV + (uint32_t)p * ASTGB;
        const size_t kvb = base + (size_t)(p * ATKV) * DMODEL;
#pragma unroll
        for (int i = 0; i < 4; i++) {
            int idx = t + i * 128, row = idx >> 3, ch = idx & 7;
            CP_ASYNC16(bo + (uint32_t)(row * ASTR + ch * 8) * 2,
                       K + kvb + (size_t)row * DMODEL + ch * 8);
            CP_ASYNC16(bo + AKVB + (uint32_t)(row * ASTR + ch * 8) * 2,
                       V + kvb + (size_t)row * DMODEL + ch * 8);
        }
        CP_COMMIT();
    }

    CP_WAIT(2);            // Q done (KV stages may be pending)
    __syncthreads();

    // Q fragments for both slabs, resident for the whole KV loop
    uint32_t qa0[4][4], qa1[4][4];
    {
        const uint32_t aq0 = (uint32_t)((warp * 32 + (lane & 15)) * ASTR + ((lane >> 4) << 3));
        const uint32_t aq1 = (uint32_t)((warp * 32 + 16 + (lane & 15)) * ASTR + ((lane >> 4) << 3));
#pragma unroll
        for (int kh = 0; kh < 4; kh++) {
            ldmx4(sQ + (aq0 + kh * 16) * 2, qa0[kh][0], qa0[kh][1], qa0[kh][2], qa0[kh][3]);
            ldmx4(sQ + (aq1 + kh * 16) * 2, qa1[kh][0], qa1[kh][1], qa1[kh][2], qa1[kh][3]);
        }
    }

    float oacc0[8][4], oacc1[8][4];
#pragma unroll
    for (int j = 0; j < 8; j++)
#pragma unroll
        for (int e = 0; e < 4; e++) { oacc0[j][e] = 0.f; oacc1[j][e] = 0.f; }
    float l0a = 0.f, l0b = 0.f, l1a = 0.f, l1b = 0.f;

    const uint32_t koff = (uint32_t)((((lane >> 4) << 3) + (lane & 7)) * ASTR
                                     + (((lane >> 3) & 1) << 3));
    const uint32_t voff = (uint32_t)((lane & 15) * ASTR + ((lane >> 4) << 3));

    int buf = 0, nbuf = 2;
    for (int it = 0; it < NKV; it++) {
        if (it + 1 < NKV) { CP_WAIT(1); } else { CP_WAIT(0); }
        __syncthreads();
        if (it + 2 < NKV) {
            const uint32_t bo = sKV + (uint32_t)nbuf * ASTGB;
            const size_t kvb = base + (size_t)((it + 2) * ATKV) * DMODEL;
#pragma unroll
            for (int i = 0; i < 4; i++) {
                int idx = t + i * 128, row = idx >> 3, ch = idx & 7;
                CP_ASYNC16(bo + (uint32_t)(row * ASTR + ch * 8) * 2,
                           K + kvb + (size_t)row * DMODEL + ch * 8);
                CP_ASYNC16(bo + AKVB + (uint32_t)(row * ASTR + ch * 8) * 2,
                           V + kvb + (size_t)row * DMODEL + ch * 8);
            }
            CP_COMMIT();
            nbuf = (nbuf == 2) ? 0 : nbuf + 1;
        }

        const uint32_t kb = sKV + (uint32_t)buf * ASTGB;
        const uint32_t vb = kb + AKVB;
        buf = (buf == 2) ? 0 : buf + 1;

        // two 32-key halves, each fully pipelined: S-MMA -> exp -> PV-MMA
#pragma unroll
        for (int half = 0; half < 2; half++) {
            float s0[4][4], s1[4][4];
#pragma unroll
            for (int j = 0; j < 4; j++)
#pragma unroll
                for (int e = 0; e < 4; e++) { s0[j][e] = 0.f; s1[j][e] = 0.f; }
#pragma unroll
            for (int kh = 0; kh < 4; kh++) {
#pragma unroll
                for (int j2l = 0; j2l < 2; j2l++) {
                    const int j2 = half * 2 + j2l;
                    uint32_t r0, r1, r2, r3;
                    ldmx4(kb + (koff + (uint32_t)(j2 * 16 * ASTR + kh * 16)) * 2,
                          r0, r1, r2, r3);
                    mma_bf16(s0[j2l*2],   qa0[kh][0], qa0[kh][1], qa0[kh][2], qa0[kh][3], r0, r1);
                    mma_bf16(s0[j2l*2+1], qa0[kh][0], qa0[kh][1], qa0[kh][2], qa0[kh][3], r2, r3);
                    mma_bf16(s1[j2l*2],   qa1[kh][0], qa1[kh][1], qa1[kh][2], qa1[kh][3], r0, r1);
                    mma_bf16(s1[j2l*2+1], qa1[kh][0], qa1[kh][1], qa1[kh][2], qa1[kh][3], r2, r3);
                }
            }
            // fixed-max softmax: p = 2^(s*CEXP)
            uint32_t pa0[2][4], pa1[2][4];
#pragma unroll
            for (int j2l = 0; j2l < 2; j2l++) {
#pragma unroll
                for (int u = 0; u < 2; u++) {
                    const int j = j2l * 2 + u;
                    float p00 = ex2(s0[j][0] * CEXP);
                    float p01 = ex2(s0[j][1] * CEXP);
                    float p02 = ex2(s0[j][2] * CEXP);
                    float p03 = ex2(s0[j][3] * CEXP);
                    l0a += p00 + p01; l0b += p02 + p03;
                    pa0[j2l][u*2]     = pack_bf16(p00, p01);
                    pa0[j2l][u*2 + 1] = pack_bf16(p02, p03);
                    float p10 = ex2(s1[j][0] * CEXP);
                    float p11 = ex2(s1[j][1] * CEXP);
                    float p12 = ex2(s1[j][2] * CEXP);
                    float p13 = ex2(s1[j][3] * CEXP);
                    l1a += p10 + p11; l1b += p12 + p13;
                    pa1[j2l][u*2]     = pack_bf16(p10, p11);
                    pa1[j2l][u*2 + 1] = pack_bf16(p12, p13);
                }
            }
            // PV for this half's 32 keys; each V fragment feeds both slabs
#pragma unroll
            for (int kkl = 0; kkl < 2; kkl++) {
                const int kk = half * 2 + kkl;
#pragma unroll
                for (int j2 = 0; j2 < 4; j2++) {
                    uint32_t r0, r1, r2, r3;
                    ldmx4t(vb + (voff + (uint32_t)(kk * 16 * ASTR + j2 * 16)) * 2,
                           r0, r1, r2, r3);
                    mma_bf16(oacc0[j2*2],   pa0[kkl][0], pa0[kkl][1], pa0[kkl][2], pa0[kkl][3], r0, r1);
                    mma_bf16(oacc0[j2*2+1], pa0[kkl][0], pa0[kkl][1], pa0[kkl][2], pa0[kkl][3], r2, r3);
                    mma_bf16(oacc1[j2*2],   pa1[kkl][0], pa1[kkl][1], pa1[kkl][2], pa1[kkl][3], r0, r1);
                    mma_bf16(oacc1[j2*2+1], pa1[kkl][0], pa1[kkl][1], pa1[kkl][2], pa1[kkl][3], r2, r3);
                }
            }
        }
    }

    l0a += __shfl_xor_sync(0xffffffffu, l0a, 1);
    l0a += __shfl_xor_sync(0xffffffffu, l0a, 2);
    l0b += __shfl_xor_sync(0xffffffffu, l0b, 1);
    l0b += __shfl_xor_sync(0xffffffffu, l0b, 2);
    l1a += __shfl_xor_sync(0xffffffffu, l1a, 1);
    l1a += __shfl_xor_sync(0xffffffffu, l1a, 2);
    l1b += __shfl_xor_sync(0xffffffffu, l1b, 1);
    l1b += __shfl_xor_sync(0xffffffffu, l1b, 2);
    const float i0a = 1.f / l0a, i0b = 1.f / l0b;
    const float i1a = 1.f / l1a, i1b = 1.f / l1b;

    const int r0r = warp * 32 + (lane >> 2);
    __nv_bfloat16* o0 = O + (size_t)(b * SEQ + q0 + r0r) * DMODEL + h * HDIM + (lane & 3) * 2;
    __nv_bfloat16* o1 = o0 + (size_t)8 * DMODEL;
    __nv_bfloat16* o2 = o0 + (size_t)16 * DMODEL;
    __nv_bfloat16* o3 = o0 + (size_t)24 * DMODEL;
#pragma unroll
    for (int jn = 0; jn < 8; jn++) {
        *(__nv_bfloat162*)(o0 + jn * 8) =
            __floats2bfloat162_rn(oacc0[jn][0] * i0a, oacc0[jn][1] * i0a);
        *(__nv_bfloat162*)(o1 + jn * 8) =
            __floats2bfloat162_rn(oacc0[jn][2] * i0b, oacc0[jn][3] * i0b);
        *(__nv_bfloat162*)(o2 + jn * 8) =
            __floats2bfloat162_rn(oacc1[jn][0] * i1a, oacc1[jn][1] * i1a);
        *(__nv_bfloat162*)(o3 + jn * 8) =
            __floats2bfloat162_rn(oacc1[jn][2] * i1b, oacc1[jn][3] * i1b);
    }
}

// ---------------------------------------------------------------------------
// fp32 -> bf16 cast (elementwise, vectorized)
// ---------------------------------------------------------------------------
__global__ __launch_bounds__(256)
void cast_bf16(const float* __restrict__ in, __nv_bfloat16* __restrict__ out, int n4)
{
    int i = blockIdx.x * blockDim.x + threadIdx.x;
    if (i >= n4) return;
    float4 v = *(const float4*)(in + (size_t)i * 4);
    *(__nv_bfloat162*)(out + (size_t)i * 4)     = __floats2bfloat162_rn(v.x, v.y);
    *(__nv_bfloat162*)(out + (size_t)i * 4 + 2) = __floats2bfloat162_rn(v.z, v.w);
}

// ---------------------------------------------------------------------------
// Transpose + cast all 4 weights: in[K,N] fp32 -> out[N,K] bf16 (z selects).
// ---------------------------------------------------------------------------
__global__ __launch_bounds__(256)
void transpose_cast4(const float* __restrict__ w0, const float* __restrict__ w1,
                     const float* __restrict__ w2, const float* __restrict__ w3,
                     __nv_bfloat16* __restrict__ oqkv, __nv_bfloat16* __restrict__ op)
{
    const int z = blockIdx.z;
    const float* in  = (z == 0) ? w0 : (z == 1) ? w1 : (z == 2) ? w2 : w3;
    __nv_bfloat16* out = (z < 3) ? (oqkv + (size_t)z * DMODEL * DMODEL) : op;
    __shared__ float tile[32][33];
    const int n0 = blockIdx.x * 32;
    const int k0 = blockIdx.y * 32;
    const int tx = threadIdx.x & 31;
    const int ty = threadIdx.x >> 5;   // 0..7
#pragma unroll
    for (int i = 0; i < 32; i += 8)
        tile[ty + i][tx] = in[(size_t)(k0 + ty + i) * DMODEL + n0 + tx];
    __syncthreads();
#pragma unroll
    for (int i = 0; i < 32; i += 8)
        out[(size_t)(n0 + ty + i) * DMODEL + k0 + tx] = __float2bfloat16(tile[tx][ty + i]);
}

// ---------------------------------------------------------------------------
// LayerNorm: one block per row (1024 elems), 256 threads, eps = 1e-6
// ---------------------------------------------------------------------------
__global__ __launch_bounds__(256)
void ln_kernel(const float* __restrict__ Y, const float* __restrict__ gamma,
               const float* __restrict__ beta, float* __restrict__ out)
{
    const int row = blockIdx.x;
    const int t = threadIdx.x;
    const float* y = Y + (size_t)row * DMODEL;

    float4 v = *(const float4*)(y + t * 4);
    float s  = v.x + v.y + v.z + v.w;
    float ss = v.x*v.x + v.y*v.y + v.z*v.z + v.w*v.w;

    __shared__ float rs[8], rss[8];
    int lane = t & 31, wid = t >> 5;
#pragma unroll
    for (int o = 16; o > 0; o >>= 1) {
        s  += __shfl_xor_sync(0xffffffffu, s,  o);
        ss += __shfl_xor_sync(0xffffffffu, ss, o);
    }
    if (lane == 0) { rs[wid] = s; rss[wid] = ss; }
    __syncthreads();
    if (wid == 0) {
        s  = (lane < 8) ? rs[lane]  : 0.f;
        ss = (lane < 8) ? rss[lane] : 0.f;
#pragma unroll
        for (int o = 4; o > 0; o >>= 1) {
            s  += __shfl_xor_sync(0xffffffffu, s,  o);
            ss += __shfl_xor_sync(0xffffffffu, ss, o);
        }
        if (lane == 0) { rs[0] = s; rss[0] = ss; }
    }
    __syncthreads();

    float mean = rs[0] * (1.f / DMODEL);
    float var  = rss[0] * (1.f / DMODEL) - mean * mean;
    float rstd = rsqrtf(var + 1e-6f);

    float4 g  = *(const float4*)(gamma + t * 4);
    float4 be = *(const float4*)(beta  + t * 4);
    float4 r;
    r.x = (v.x - mean) * rstd * g.x + be.x;
    r.y = (v.y - mean) * rstd * g.y + be.y;
    r.z = (v.z - mean) * rstd * g.z + be.z;
    r.w = (v.w - mean) * rstd * g.w + be.w;
    *(float4*)(out + (size_t)row * DMODEL + t * 4) = r;
}

// ---------------------------------------------------------------------------
// Launch
// ---------------------------------------------------------------------------
extern "C" void kernel_launch(void* const* d_in, const int* in_sizes, int n_in,
                              void* d_out, int out_size)
{
    const float* x      = (const float*)d_in[0];
    const float* w_q    = (const float*)d_in[1];
    const float* w_k    = (const float*)d_in[2];
    const float* w_v    = (const float*)d_in[3];
    const float* w_proj = (const float*)d_in[4];
    const float* b_proj = (const float*)d_in[5];
    const float* gamma  = (const float*)d_in[6];
    const float* beta   = (const float*)d_in[7];
    float* out = (float*)d_out;

    float* y;
    __nv_bfloat16 *xb, *qkvb, *ob, *wqkv, *wpb;
    cudaGetSymbolAddress((void**)&y,    g_y);
    cudaGetSymbolAddress((void**)&xb,   g_xb);
    cudaGetSymbolAddress((void**)&qkvb, g_qkvb);
    cudaGetSymbolAddress((void**)&ob,   g_ob);
    cudaGetSymbolAddress((void**)&wqkv, g_wqkv);
    cudaGetSymbolAddress((void**)&wpb,  g_wpb);

    cudaFuncSetAttribute(gemm_mma<0>, cudaFuncAttributeMaxDynamicSharedMemorySize, GSMEM);
    cudaFuncSetAttribute(gemm_mma<1>, cudaFuncAttributeMaxDynamicSharedMemorySize, GSMEM);
    cudaFuncSetAttribute(attn_mma, cudaFuncAttributeMaxDynamicSharedMemorySize, ASMEM);

    // Casts / weight transposes
    const int n4 = MROWS * DMODEL / 4;
    cast_bf16<<<(n4 + 255) / 256, 256>>>(x, xb, n4);
    dim3 tg(DMODEL / 32, DMODEL / 32, 4);
    transpose_cast4<<<tg, 256>>>(w_q, w_k, w_v, w_proj, wqkv, wpb);

    // Fused QKV projection (bf16 out, split into q/k/v regions)
    dim3 gq(3 * DMODEL / BN, MROWS / BM);   // (24, 64)
    gemm_mma<0><<<gq, 256, GSMEM>>>(xb, wqkv, qkvb, nullptr, nullptr);

    // Flash attention on tensor cores (fixed-max softmax, fused half-PV)
    dim3 ga(SEQ / ATQ, NHEAD, BATCH);       // (16, 16, 4)
    attn_mma<<<ga, 128, ASMEM>>>(qkvb, qkvb + (size_t)MROWS * DMODEL,
                                 qkvb + (size_t)2 * MROWS * DMODEL, ob);

    // proj + bias + residual (fp32 out)
    dim3 gp(DMODEL / BN, MROWS / BM);       // (8, 64)
    gemm_mma<1><<<gp, 256, GSMEM>>>(ob, wpb, y, b_proj, x);

    ln_kernel<<<MROWS, 256>>>(y, gamma, beta, out);
}

// round 14
// speedup vs baseline: 1.6033x; 1.0765x over previous
#include <cuda_runtime.h>
#include <cuda_bf16.h>
#include <cstdint>

// Problem dims (fixed)
#define BATCH  4
#define SEQ    2048
#define DMODEL 1024
#define NHEAD  16
#define HDIM   64
#define MROWS  (BATCH*SEQ)   // 8192

// ---------------------------------------------------------------------------
// Scratch (device-static: allocation-free per harness rules)
// ---------------------------------------------------------------------------
__device__ float g_y[(size_t)MROWS*DMODEL];
__device__ __nv_bfloat16 g_xb[(size_t)MROWS*DMODEL];
__device__ __nv_bfloat16 g_qkvb[(size_t)3*MROWS*DMODEL];
__device__ __nv_bfloat16 g_ob[(size_t)MROWS*DMODEL];
__device__ __nv_bfloat16 g_wqkv[(size_t)3*DMODEL*DMODEL];  // [3*N, K] transposed
__device__ __nv_bfloat16 g_wpb[(size_t)DMODEL*DMODEL];

// ---------------------------------------------------------------------------
// PTX helpers (base ISA only — sm_103 target has no tcgen05)
// ---------------------------------------------------------------------------
__device__ __forceinline__ uint32_t smem_u32(const void* p) {
    uint32_t a;
    asm("{ .reg .u64 t; cvta.to.shared.u64 t, %1; cvt.u32.u64 %0, t; }" : "=r"(a) : "l"(p));
    return a;
}
#define CP_ASYNC16(dst, src) \
    asm volatile("cp.async.cg.shared.global [%0], [%1], 16;" :: "r"(dst), "l"(src))
#define CP_COMMIT()   asm volatile("cp.async.commit_group;")
#define CP_WAIT(N)    asm volatile("cp.async.wait_group %0;" :: "n"(N))

__device__ __forceinline__ void ldmx4(uint32_t addr, uint32_t& r0, uint32_t& r1,
                                      uint32_t& r2, uint32_t& r3) {
    asm volatile("ldmatrix.sync.aligned.m8n8.x4.shared.b16 {%0,%1,%2,%3}, [%4];"
                 : "=r"(r0), "=r"(r1), "=r"(r2), "=r"(r3) : "r"(addr));
}
__device__ __forceinline__ void ldmx4t(uint32_t addr, uint32_t& r0, uint32_t& r1,
                                       uint32_t& r2, uint32_t& r3) {
    asm volatile("ldmatrix.sync.aligned.m8n8.x4.trans.shared.b16 {%0,%1,%2,%3}, [%4];"
                 : "=r"(r0), "=r"(r1), "=r"(r2), "=r"(r3) : "r"(addr));
}
__device__ __forceinline__ void mma_bf16(float c[4], uint32_t a0, uint32_t a1,
                                         uint32_t a2, uint32_t a3,
                                         uint32_t b0, uint32_t b1) {
    asm volatile("mma.sync.aligned.m16n8k16.row.col.f32.bf16.bf16.f32 "
                 "{%0,%1,%2,%3}, {%4,%5,%6,%7}, {%8,%9}, {%0,%1,%2,%3};"
                 : "+f"(c[0]), "+f"(c[1]), "+f"(c[2]), "+f"(c[3])
                 : "r"(a0), "r"(a1), "r"(a2), "r"(a3), "r"(b0), "r"(b1));
}
__device__ __forceinline__ float ex2(float x) {
    float y; asm("ex2.approx.ftz.f32 %0, %1;" : "=f"(y) : "f"(x)); return y;
}
__device__ __forceinline__ uint32_t pack_bf16(float a, float b) {
    __nv_bfloat162 v = __floats2bfloat162_rn(a, b);
    return *(uint32_t*)&v;
}

// ---------------------------------------------------------------------------
// bf16 mma.sync GEMM: C = A[M,K] @ Bt[N,K]^T, 128x128 tile, BK=64,
// 3-stage cp.async ring, ONE __syncthreads per K-iteration (16 iters:
// half the barrier count of BK=32 for the same MMA work).
// Row stride 72 bf16 (144 B) -> ldmatrix conflict-free.
// MODE 0: bf16 out, N=3072 fused QKV. MODE 1: fp32 out + bias + resid.
// ---------------------------------------------------------------------------
#define BM  128
#define BN  128
#define BKK 64
#define GSTR 72
#define NITER (DMODEL / BKK)          // 16
#define STGB  (BM * GSTR * 2)         // 18432 B per operand per stage
#define GSTG  (2 * STGB)              // 36864 B per stage (A + B)
#define GSMEM (3 * GSTG)              // 110592 B

template<int MODE>
__global__ __launch_bounds__(256)
void gemm_mma(const __nv_bfloat16* __restrict__ A, const __nv_bfloat16* __restrict__ Bt,
              void* __restrict__ Cv, const float* __restrict__ bias,
              const float* __restrict__ resid)
{
    extern __shared__ char gsm[];
    const uint32_t sS = smem_u32(gsm);

    const int t    = threadIdx.x;
    const int lane = t & 31;
    const int warp = t >> 5;
    const int wm   = (warp >> 2) * 64;
    const int wn   = (warp & 3) * 32;
    const int bm   = blockIdx.y * BM;
    const int bn   = blockIdx.x * BN;

    // cp.async mapping: per operand per stage, 128 rows x 8 chunks(16B) = 1024
    // chunks; 256 threads -> 4 chunks each (i-strided).
    const __nv_bfloat16* ag[4];
    const __nv_bfloat16* bg[4];
    uint32_t ds[4];
#pragma unroll
    for (int i = 0; i < 4; i++) {
        const int c = t + i * 256;          // 0..1023
        const int row = c >> 3;
        const int col = (c & 7) * 8;        // bf16 elements
        ag[i] = A  + (size_t)(bm + row) * DMODEL + col;
        bg[i] = Bt + (size_t)(bn + row) * DMODEL + col;
        ds[i] = (uint32_t)(row * GSTR + col) * 2;
    }

    float acc[4][4][4];
#pragma unroll
    for (int i = 0; i < 4; i++)
#pragma unroll
        for (int j = 0; j < 4; j++)
#pragma unroll
            for (int e = 0; e < 4; e++) acc[i][j][e] = 0.f;

    // prologue: stages 0,1
#pragma unroll
    for (int p = 0; p < 2; p++) {
        const uint32_t bo = sS + (uint32_t)p * GSTG;
        const int ko = p * BKK;
#pragma unroll
        for (int i = 0; i < 4; i++) {
            CP_ASYNC16(bo + ds[i], ag[i] + ko);
            CP_ASYNC16(bo + STGB + ds[i], bg[i] + ko);
        }
        CP_COMMIT();
    }

    const uint32_t aoff = (uint32_t)((wm + (lane & 15)) * GSTR + ((lane >> 4) << 3)) * 2;
    const uint32_t boff = STGB + (uint32_t)((wn + ((lane >> 4) << 3) + (lane & 7)) * GSTR
                                            + (((lane >> 3) & 1) << 3)) * 2;

    int buf = 0, nbuf = 2;
    for (int it = 0; it < NITER; it++) {
        if (it + 1 < NITER) { CP_WAIT(1); } else { CP_WAIT(0); }
        __syncthreads();
        if (it + 2 < NITER) {
            const uint32_t bo = sS + (uint32_t)nbuf * GSTG;
            const int ko = (it + 2) * BKK;
#pragma unroll
            for (int i = 0; i < 4; i++) {
                CP_ASYNC16(bo + ds[i], ag[i] + ko);
                CP_ASYNC16(bo + STGB + ds[i], bg[i] + ko);
            }
            CP_COMMIT();
            nbuf = (nbuf == 2) ? 0 : nbuf + 1;
        }

        const uint32_t base = sS + (uint32_t)buf * GSTG;
        buf = (buf == 2) ? 0 : buf + 1;
#pragma unroll
        for (int kh = 0; kh < 4; kh++) {           // 4 x k16 per BK=64
            uint32_t a[4][4], bfr[4][2];
#pragma unroll
            for (int mi = 0; mi < 4; mi++) {
                uint32_t addr = base + aoff + (uint32_t)(mi * 16 * GSTR + kh * 16) * 2;
                ldmx4(addr, a[mi][0], a[mi][1], a[mi][2], a[mi][3]);
            }
#pragma unroll
            for (int j = 0; j < 2; j++) {
                uint32_t addr = base + boff + (uint32_t)(j * 16 * GSTR + kh * 16) * 2;
                uint32_t r0, r1, r2, r3;
                ldmx4(addr, r0, r1, r2, r3);
                bfr[j*2][0] = r0; bfr[j*2][1] = r1;
                bfr[j*2+1][0] = r2; bfr[j*2+1][1] = r3;
            }
#pragma unroll
            for (int mi = 0; mi < 4; mi++)
#pragma unroll
                for (int ni = 0; ni < 4; ni++)
                    mma_bf16(acc[mi][ni], a[mi][0], a[mi][1], a[mi][2], a[mi][3],
                             bfr[ni][0], bfr[ni][1]);
        }
    }

    // epilogue
    const int r0 = bm + wm + (lane >> 2);
#pragma unroll
    for (int mi = 0; mi < 4; mi++) {
#pragma unroll
        for (int ni = 0; ni < 4; ni++) {
            const int row = r0 + mi * 16;
            if constexpr (MODE == 0) {
                __nv_bfloat16* Cb = (__nv_bfloat16*)Cv
                    + (size_t)(bn >> 10) * MROWS * DMODEL;
                const int col = (bn & 1023) + wn + (lane & 3) * 2 + ni * 8;
                *(__nv_bfloat162*)(Cb + (size_t)row * DMODEL + col) =
                    __floats2bfloat162_rn(acc[mi][ni][0], acc[mi][ni][1]);
                *(__nv_bfloat162*)(Cb + (size_t)(row + 8) * DMODEL + col) =
                    __floats2bfloat162_rn(acc[mi][ni][2], acc[mi][ni][3]);
            } else {
                float* Cf = (float*)Cv;
                const int col = bn + wn + (lane & 3) * 2 + ni * 8;
                float2 v0 = make_float2(acc[mi][ni][0], acc[mi][ni][1]);
                float2 v1 = make_float2(acc[mi][ni][2], acc[mi][ni][3]);
                const float2 bb = *(const float2*)(bias + col);
                const float2 x0 = *(const float2*)(resid + (size_t)row * DMODEL + col);
                const float2 x1 = *(const float2*)(resid + (size_t)(row + 8) * DMODEL + col);
                v0.x += bb.x + x0.x; v0.y += bb.y + x0.y;
                v1.x += bb.x + x1.x; v1.y += bb.y + x1.y;
                *(float2*)(Cf + (size_t)row * DMODEL + col)       = v0;
                *(float2*)(Cf + (size_t)(row + 8) * DMODEL + col) = v1;
            }
        }
    }
}

// ---------------------------------------------------------------------------
// Flash attention on mma.sync (bf16 in/out, fp32 accum), fixed-max softmax.
// R10 best configuration: 128 threads, 4 warps, 2 slabs/warp, pa[4][4],
// 3-stage KV ring, no launch-bounds cap.
// ---------------------------------------------------------------------------
#define ATQ   128
#define ATKV  64
#define ASTR  72
#define AQBYTES  (ATQ * ASTR * 2)          // 18432
#define AKVB     (ATKV * ASTR * 2)         // 9216 (per tensor)
#define ASTGB    (2 * AKVB)                // 18432 (K + V per stage)
#define ASMEM    (AQBYTES + 3 * ASTGB)     // 73728
#define CEXP  0.180336880f                 // 0.125 * log2(e)
#define NKV   (SEQ / ATKV)                 // 32

__global__ __launch_bounds__(128)
void attn_mma(const __nv_bfloat16* __restrict__ Q, const __nv_bfloat16* __restrict__ K,
              const __nv_bfloat16* __restrict__ V, __nv_bfloat16* __restrict__ O)
{
    extern __shared__ char smattn[];
    const uint32_t sQ = smem_u32(smattn);
    const uint32_t sKV = sQ + AQBYTES;     // stage s: K at s*ASTGB, V at +AKVB

    const int t = threadIdx.x, lane = t & 31, warp = t >> 5;   // warp 0..3
    const int b = blockIdx.z, h = blockIdx.y;
    const int q0 = blockIdx.x * ATQ;
    const size_t base = (size_t)b * SEQ * DMODEL + (size_t)h * HDIM;

    // prologue: Q (1 group), KV stages 0,1 (1 group each). 128 threads.
#pragma unroll
    for (int i = 0; i < 8; i++) {
        int idx = t + i * 128, row = idx >> 3, ch = idx & 7;
        CP_ASYNC16(sQ + (uint32_t)(row * ASTR + ch * 8) * 2,
                   Q + base + (size_t)(q0 + row) * DMODEL + ch * 8);
    }
    CP_COMMIT();
#pragma unroll
    for (int p = 0; p < 2; p++) {
        const uint32_t bo = sKV + (uint32_t)p * ASTGB;
        const size_t kvb = base + (size_t)(p * ATKV) * DMODEL;
#pragma unroll
        for (int i = 0; i < 4; i++) {
            int idx = t + i * 128, row = idx >> 3, ch = idx & 7;
            CP_ASYNC16(bo + (uint32_t)(row * ASTR + ch * 8) * 2,
                       K + kvb + (size_t)row * DMODEL + ch * 8);
            CP_ASYNC16(bo + AKVB + (uint32_t)(row * ASTR + ch * 8) * 2,
                       V + kvb + (size_t)row * DMODEL + ch * 8);
        }
        CP_COMMIT();
    }

    CP_WAIT(2);            // Q done (KV stages may be pending)
    __syncthreads();

    // Q fragments for both slabs, resident for the whole KV loop
    uint32_t qa0[4][4], qa1[4][4];
    {
        const uint32_t aq0 = (uint32_t)((warp * 32 + (lane & 15)) * ASTR + ((lane >> 4) << 3));
        const uint32_t aq1 = (uint32_t)((warp * 32 + 16 + (lane & 15)) * ASTR + ((lane >> 4) << 3));
#pragma unroll
        for (int kh = 0; kh < 4; kh++) {
            ldmx4(sQ + (aq0 + kh * 16) * 2, qa0[kh][0], qa0[kh][1], qa0[kh][2], qa0[kh][3]);
            ldmx4(sQ + (aq1 + kh * 16) * 2, qa1[kh][0], qa1[kh][1], qa1[kh][2], qa1[kh][3]);
        }
    }

    float oacc0[8][4], oacc1[8][4];
#pragma unroll
    for (int j = 0; j < 8; j++)
#pragma unroll
        for (int e = 0; e < 4; e++) { oacc0[j][e] = 0.f; oacc1[j][e] = 0.f; }
    float l0a = 0.f, l0b = 0.f, l1a = 0.f, l1b = 0.f;

    const uint32_t koff = (uint32_t)((((lane >> 4) << 3) + (lane & 7)) * ASTR
                                     + (((lane >> 3) & 1) << 3));
    const uint32_t voff = (uint32_t)((lane & 15) * ASTR + ((lane >> 4) << 3));

    int buf = 0, nbuf = 2;
    for (int it = 0; it < NKV; it++) {
        if (it + 1 < NKV) { CP_WAIT(1); } else { CP_WAIT(0); }
        __syncthreads();
        if (it + 2 < NKV) {
            const uint32_t bo = sKV + (uint32_t)nbuf * ASTGB;
            const size_t kvb = base + (size_t)((it + 2) * ATKV) * DMODEL;
#pragma unroll
            for (int i = 0; i < 4; i++) {
                int idx = t + i * 128, row = idx >> 3, ch = idx & 7;
                CP_ASYNC16(bo + (uint32_t)(row * ASTR + ch * 8) * 2,
                           K + kvb + (size_t)row * DMODEL + ch * 8);
                CP_ASYNC16(bo + AKVB + (uint32_t)(row * ASTR + ch * 8) * 2,
                           V + kvb + (size_t)row * DMODEL + ch * 8);
            }
            CP_COMMIT();
            nbuf = (nbuf == 2) ? 0 : nbuf + 1;
        }

        const uint32_t kb = sKV + (uint32_t)buf * ASTGB;
        const uint32_t vb = kb + AKVB;
        buf = (buf == 2) ? 0 : buf + 1;

        uint32_t pa0[4][4], pa1[4][4];
        // S = Q @ K^T in two n-halves (keys [0,32) then [32,64)) to cap regs
#pragma unroll
        for (int half = 0; half < 2; half++) {
            float s0[4][4], s1[4][4];
#pragma unroll
            for (int j = 0; j < 4; j++)
#pragma unroll
                for (int e = 0; e < 4; e++) { s0[j][e] = 0.f; s1[j][e] = 0.f; }
#pragma unroll
            for (int kh = 0; kh < 4; kh++) {
#pragma unroll
                for (int j2l = 0; j2l < 2; j2l++) {
                    const int j2 = half * 2 + j2l;
                    uint32_t r0, r1, r2, r3;
                    ldmx4(kb + (koff + (uint32_t)(j2 * 16 * ASTR + kh * 16)) * 2,
                          r0, r1, r2, r3);
                    mma_bf16(s0[j2l*2],   qa0[kh][0], qa0[kh][1], qa0[kh][2], qa0[kh][3], r0, r1);
                    mma_bf16(s0[j2l*2+1], qa0[kh][0], qa0[kh][1], qa0[kh][2], qa0[kh][3], r2, r3);
                    mma_bf16(s1[j2l*2],   qa1[kh][0], qa1[kh][1], qa1[kh][2], qa1[kh][3], r0, r1);
                    mma_bf16(s1[j2l*2+1], qa1[kh][0], qa1[kh][1], qa1[kh][2], qa1[kh][3], r2, r3);
                }
            }
            // fixed-max softmax: p = 2^(s*CEXP)
#pragma unroll
            for (int j2l = 0; j2l < 2; j2l++) {
#pragma unroll
                for (int u = 0; u < 2; u++) {
                    const int j = j2l * 2 + u;
                    float p00 = ex2(s0[j][0] * CEXP);
                    float p01 = ex2(s0[j][1] * CEXP);
                    float p02 = ex2(s0[j][2] * CEXP);
                    float p03 = ex2(s0[j][3] * CEXP);
                    l0a += p00 + p01; l0b += p02 + p03;
                    pa0[half*2 + j2l][u*2]     = pack_bf16(p00, p01);
                    pa0[half*2 + j2l][u*2 + 1] = pack_bf16(p02, p03);
                    float p10 = ex2(s1[j][0] * CEXP);
                    float p11 = ex2(s1[j][1] * CEXP);
                    float p12 = ex2(s1[j][2] * CEXP);
                    float p13 = ex2(s1[j][3] * CEXP);
                    l1a += p10 + p11; l1b += p12 + p13;
                    pa1[half*2 + j2l][u*2]     = pack_bf16(p10, p11);
                    pa1[half*2 + j2l][u*2 + 1] = pack_bf16(p12, p13);
                }
            }
        }

        // O += P @ V (un-normalized); each V fragment feeds both slabs
#pragma unroll
        for (int kk = 0; kk < 4; kk++) {
#pragma unroll
            for (int j2 = 0; j2 < 4; j2++) {
                uint32_t r0, r1, r2, r3;
                ldmx4t(vb + (voff + (uint32_t)(kk * 16 * ASTR + j2 * 16)) * 2, r0, r1, r2, r3);
                mma_bf16(oacc0[j2*2],   pa0[kk][0], pa0[kk][1], pa0[kk][2], pa0[kk][3], r0, r1);
                mma_bf16(oacc0[j2*2+1], pa0[kk][0], pa0[kk][1], pa0[kk][2], pa0[kk][3], r2, r3);
                mma_bf16(oacc1[j2*2],   pa1[kk][0], pa1[kk][1], pa1[kk][2], pa1[kk][3], r0, r1);
                mma_bf16(oacc1[j2*2+1], pa1[kk][0], pa1[kk][1], pa1[kk][2], pa1[kk][3], r2, r3);
            }
        }
    }

    l0a += __shfl_xor_sync(0xffffffffu, l0a, 1);
    l0a += __shfl_xor_sync(0xffffffffu, l0a, 2);
    l0b += __shfl_xor_sync(0xffffffffu, l0b, 1);
    l0b += __shfl_xor_sync(0xffffffffu, l0b, 2);
    l1a += __shfl_xor_sync(0xffffffffu, l1a, 1);
    l1a += __shfl_xor_sync(0xffffffffu, l1a, 2);
    l1b += __shfl_xor_sync(0xffffffffu, l1b, 1);
    l1b += __shfl_xor_sync(0xffffffffu, l1b, 2);
    const float i0a = 1.f / l0a, i0b = 1.f / l0b;
    const float i1a = 1.f / l1a, i1b = 1.f / l1b;

    const int r0r = warp * 32 + (lane >> 2);
    __nv_bfloat16* o0 = O + (size_t)(b * SEQ + q0 + r0r) * DMODEL + h * HDIM + (lane & 3) * 2;
    __nv_bfloat16* o1 = o0 + (size_t)8 * DMODEL;
    __nv_bfloat16* o2 = o0 + (size_t)16 * DMODEL;
    __nv_bfloat16* o3 = o0 + (size_t)24 * DMODEL;
#pragma unroll
    for (int jn = 0; jn < 8; jn++) {
        *(__nv_bfloat162*)(o0 + jn * 8) =
            __floats2bfloat162_rn(oacc0[jn][0] * i0a, oacc0[jn][1] * i0a);
        *(__nv_bfloat162*)(o1 + jn * 8) =
            __floats2bfloat162_rn(oacc0[jn][2] * i0b, oacc0[jn][3] * i0b);
        *(__nv_bfloat162*)(o2 + jn * 8) =
            __floats2bfloat162_rn(oacc1[jn][0] * i1a, oacc1[jn][1] * i1a);
        *(__nv_bfloat162*)(o3 + jn * 8) =
            __floats2bfloat162_rn(oacc1[jn][2] * i1b, oacc1[jn][3] * i1b);
    }
}

// ---------------------------------------------------------------------------
// fp32 -> bf16 cast (elementwise, vectorized)
// ---------------------------------------------------------------------------
__global__ __launch_bounds__(256)
void cast_bf16(const float* __restrict__ in, __nv_bfloat16* __restrict__ out, int n4)
{
    int i = blockIdx.x * blockDim.x + threadIdx.x;
    if (i >= n4) return;
    float4 v = *(const float4*)(in + (size_t)i * 4);
    *(__nv_bfloat162*)(out + (size_t)i * 4)     = __floats2bfloat162_rn(v.x, v.y);
    *(__nv_bfloat162*)(out + (size_t)i * 4 + 2) = __floats2bfloat162_rn(v.z, v.w);
}

// ---------------------------------------------------------------------------
// Transpose + cast all 4 weights: in[K,N] fp32 -> out[N,K] bf16 (z selects).
// ---------------------------------------------------------------------------
__global__ __launch_bounds__(256)
void transpose_cast4(const float* __restrict__ w0, const float* __restrict__ w1,
                     const float* __restrict__ w2, const float* __restrict__ w3,
                     __nv_bfloat16* __restrict__ oqkv, __nv_bfloat16* __restrict__ op)
{
    const int z = blockIdx.z;
    const float* in  = (z == 0) ? w0 : (z == 1) ? w1 : (z == 2) ? w2 : w3;
    __nv_bfloat16* out = (z < 3) ? (oqkv + (size_t)z * DMODEL * DMODEL) : op;
    __shared__ float tile[32][33];
    const int n0 = blockIdx.x * 32;
    const int k0 = blockIdx.y * 32;
    const int tx = threadIdx.x & 31;
    const int ty = threadIdx.x >> 5;   // 0..7
#pragma unroll
    for (int i = 0; i < 32; i += 8)
        tile[ty + i][tx] = in[(size_t)(k0 + ty + i) * DMODEL + n0 + tx];
    __syncthreads();
#pragma unroll
    for (int i = 0; i < 32; i += 8)
        out[(size_t)(n0 + ty + i) * DMODEL + k0 + tx] = __float2bfloat16(tile[tx][ty + i]);
}

// ---------------------------------------------------------------------------
// LayerNorm: one block per row (1024 elems), 256 threads, eps = 1e-6
// ---------------------------------------------------------------------------
__global__ __launch_bounds__(256)
void ln_kernel(const float* __restrict__ Y, const float* __restrict__ gamma,
               const float* __restrict__ beta, float* __restrict__ out)
{
    const int row = blockIdx.x;
    const int t = threadIdx.x;
    const float* y = Y + (size_t)row * DMODEL;

    float4 v = *(const float4*)(y + t * 4);
    float s  = v.x + v.y + v.z + v.w;
    float ss = v.x*v.x + v.y*v.y + v.z*v.z + v.w*v.w;

    __shared__ float rs[8], rss[8];
    int lane = t & 31, wid = t >> 5;
#pragma unroll
    for (int o = 16; o > 0; o >>= 1) {
        s  += __shfl_xor_sync(0xffffffffu, s,  o);
        ss += __shfl_xor_sync(0xffffffffu, ss, o);
    }
    if (lane == 0) { rs[wid] = s; rss[wid] = ss; }
    __syncthreads();
    if (wid == 0) {
        s  = (lane < 8) ? rs[lane]  : 0.f;
        ss = (lane < 8) ? rss[lane] : 0.f;
#pragma unroll
        for (int o = 4; o > 0; o >>= 1) {
            s  += __shfl_xor_sync(0xffffffffu, s,  o);
            ss += __shfl_xor_sync(0xffffffffu, ss, o);
        }
        if (lane == 0) { rs[0] = s; rss[0] = ss; }
    }
    __syncthreads();

    float mean = rs[0] * (1.f / DMODEL);
    float var  = rss[0] * (1.f / DMODEL) - mean * mean;
    float rstd = rsqrtf(var + 1e-6f);

    float4 g  = *(const float4*)(gamma + t * 4);
    float4 be = *(const float4*)(beta  + t * 4);
    float4 r;
    r.x = (v.x - mean) * rstd * g.x + be.x;
    r.y = (v.y - mean) * rstd * g.y + be.y;
    r.z = (v.z - mean) * rstd * g.z + be.z;
    r.w = (v.w - mean) * rstd * g.w + be.w;
    *(float4*)(out + (size_t)row * DMODEL + t * 4) = r;
}

// ---------------------------------------------------------------------------
// Launch
// ---------------------------------------------------------------------------
extern "C" void kernel_launch(void* const* d_in, const int* in_sizes, int n_in,
                              void* d_out, int out_size)
{
    const float* x      = (const float*)d_in[0];
    const float* w_q    = (const float*)d_in[1];
    const float* w_k    = (const float*)d_in[2];
    const float* w_v    = (const float*)d_in[3];
    const float* w_proj = (const float*)d_in[4];
    const float* b_proj = (const float*)d_in[5];
    const float* gamma  = (const float*)d_in[6];
    const float* beta   = (const float*)d_in[7];
    float* out = (float*)d_out;

    float* y;
    __nv_bfloat16 *xb, *qkvb, *ob, *wqkv, *wpb;
    cudaGetSymbolAddress((void**)&y,    g_y);
    cudaGetSymbolAddress((void**)&xb,   g_xb);
    cudaGetSymbolAddress((void**)&qkvb, g_qkvb);
    cudaGetSymbolAddress((void**)&ob,   g_ob);
    cudaGetSymbolAddress((void**)&wqkv, g_wqkv);
    cudaGetSymbolAddress((void**)&wpb,  g_wpb);

    cudaFuncSetAttribute(gemm_mma<0>, cudaFuncAttributeMaxDynamicSharedMemorySize, GSMEM);
    cudaFuncSetAttribute(gemm_mma<1>, cudaFuncAttributeMaxDynamicSharedMemorySize, GSMEM);
    cudaFuncSetAttribute(attn_mma, cudaFuncAttributeMaxDynamicSharedMemorySize, ASMEM);

    // Casts / weight transposes
    const int n4 = MROWS * DMODEL / 4;
    cast_bf16<<<(n4 + 255) / 256, 256>>>(x, xb, n4);
    dim3 tg(DMODEL / 32, DMODEL / 32, 4);
    transpose_cast4<<<tg, 256>>>(w_q, w_k, w_v, w_proj, wqkv, wpb);

    // Fused QKV projection (bf16 out, split into q/k/v regions)
    dim3 gq(3 * DMODEL / BN, MROWS / BM);   // (24, 64)
    gemm_mma<0><<<gq, 256, GSMEM>>>(xb, wqkv, qkvb, nullptr, nullptr);

    // Flash attention on tensor cores (fixed-max softmax, 2 slabs/warp)
    dim3 ga(SEQ / ATQ, NHEAD, BATCH);       // (16, 16, 4)
    attn_mma<<<ga, 128, ASMEM>>>(qkvb, qkvb + (size_t)MROWS * DMODEL,
                                 qkvb + (size_t)2 * MROWS * DMODEL, ob);

    // proj + bias + residual (fp32 out)
    dim3 gp(DMODEL / BN, MROWS / BM);       // (8, 64)
    gemm_mma<1><<<gp, 256, GSMEM>>>(ob, wpb, y, b_proj, x);

    ln_kernel<<<MROWS, 256>>>(y, gamma, beta, out);
}

// round 16
// speedup vs baseline: 1.6220x; 1.0117x over previous
#include <cuda_runtime.h>
#include <cuda_bf16.h>
#include <cstdint>

// Problem dims (fixed)
#define BATCH  4
#define SEQ    2048
#define DMODEL 1024
#define NHEAD  16
#define HDIM   64
#define MROWS  (BATCH*SEQ)   // 8192

// ---------------------------------------------------------------------------
// Scratch (device-static: allocation-free per harness rules)
// ---------------------------------------------------------------------------
__device__ float g_y[(size_t)MROWS*DMODEL];
__device__ __nv_bfloat16 g_xb[(size_t)MROWS*DMODEL];
__device__ __nv_bfloat16 g_qkvb[(size_t)3*MROWS*DMODEL];
__device__ __nv_bfloat16 g_ob[(size_t)MROWS*DMODEL];
__device__ __nv_bfloat16 g_wqkv[(size_t)3*DMODEL*DMODEL];  // [3*N, K] transposed
__device__ __nv_bfloat16 g_wpb[(size_t)DMODEL*DMODEL];

// ---------------------------------------------------------------------------
// PTX helpers (base ISA only — sm_103 target has no tcgen05)
// ---------------------------------------------------------------------------
__device__ __forceinline__ uint32_t smem_u32(const void* p) {
    uint32_t a;
    asm("{ .reg .u64 t; cvta.to.shared.u64 t, %1; cvt.u32.u64 %0, t; }" : "=r"(a) : "l"(p));
    return a;
}
#define CP_ASYNC16(dst, src) \
    asm volatile("cp.async.cg.shared.global [%0], [%1], 16;" :: "r"(dst), "l"(src))
#define CP_COMMIT()   asm volatile("cp.async.commit_group;")
#define CP_WAIT(N)    asm volatile("cp.async.wait_group %0;" :: "n"(N))

__device__ __forceinline__ void ldmx4(uint32_t addr, uint32_t& r0, uint32_t& r1,
                                      uint32_t& r2, uint32_t& r3) {
    asm volatile("ldmatrix.sync.aligned.m8n8.x4.shared.b16 {%0,%1,%2,%3}, [%4];"
                 : "=r"(r0), "=r"(r1), "=r"(r2), "=r"(r3) : "r"(addr));
}
__device__ __forceinline__ void ldmx4t(uint32_t addr, uint32_t& r0, uint32_t& r1,
                                       uint32_t& r2, uint32_t& r3) {
    asm volatile("ldmatrix.sync.aligned.m8n8.x4.trans.shared.b16 {%0,%1,%2,%3}, [%4];"
                 : "=r"(r0), "=r"(r1), "=r"(r2), "=r"(r3) : "r"(addr));
}
__device__ __forceinline__ void mma_bf16(float c[4], uint32_t a0, uint32_t a1,
                                         uint32_t a2, uint32_t a3,
                                         uint32_t b0, uint32_t b1) {
    asm volatile("mma.sync.aligned.m16n8k16.row.col.f32.bf16.bf16.f32 "
                 "{%0,%1,%2,%3}, {%4,%5,%6,%7}, {%8,%9}, {%0,%1,%2,%3};"
                 : "+f"(c[0]), "+f"(c[1]), "+f"(c[2]), "+f"(c[3])
                 : "r"(a0), "r"(a1), "r"(a2), "r"(a3), "r"(b0), "r"(b1));
}
__device__ __forceinline__ float ex2(float x) {
    float y; asm("ex2.approx.ftz.f32 %0, %1;" : "=f"(y) : "f"(x)); return y;
}
__device__ __forceinline__ uint32_t pack_bf16(float a, float b) {
    __nv_bfloat162 v = __floats2bfloat162_rn(a, b);
    return *(uint32_t*)&v;
}

// ---------------------------------------------------------------------------
// bf16 mma.sync GEMM: C = A[M,K] @ Bt[N,K]^T, 128x128 tile, BK=64,
// 3-stage cp.async ring, ONE __syncthreads per K-iteration (16 iters).
// Row stride 72 bf16 (144 B) -> ldmatrix conflict-free.
// MODE 0: bf16 out, N=3072 fused QKV. MODE 1: fp32 out + bias + resid.
// ---------------------------------------------------------------------------
#define BM  128
#define BN  128
#define BKK 64
#define GSTR 72
#define NITER (DMODEL / BKK)          // 16
#define STGB  (BM * GSTR * 2)         // 18432 B per operand per stage
#define GSTG  (2 * STGB)              // 36864 B per stage (A + B)
#define GSMEM (3 * GSTG)              // 110592 B

template<int MODE>
__global__ __launch_bounds__(256)
void gemm_mma(const __nv_bfloat16* __restrict__ A, const __nv_bfloat16* __restrict__ Bt,
              void* __restrict__ Cv, const float* __restrict__ bias,
              const float* __restrict__ resid)
{
    extern __shared__ char gsm[];
    const uint32_t sS = smem_u32(gsm);

    const int t    = threadIdx.x;
    const int lane = t & 31;
    const int warp = t >> 5;
    const int wm   = (warp >> 2) * 64;
    const int wn   = (warp & 3) * 32;
    const int bm   = blockIdx.y * BM;
    const int bn   = blockIdx.x * BN;

    const __nv_bfloat16* ag[4];
    const __nv_bfloat16* bg[4];
    uint32_t ds[4];
#pragma unroll
    for (int i = 0; i < 4; i++) {
        const int c = t + i * 256;          // 0..1023
        const int row = c >> 3;
        const int col = (c & 7) * 8;
        ag[i] = A  + (size_t)(bm + row) * DMODEL + col;
        bg[i] = Bt + (size_t)(bn + row) * DMODEL + col;
        ds[i] = (uint32_t)(row * GSTR + col) * 2;
    }

    float acc[4][4][4];
#pragma unroll
    for (int i = 0; i < 4; i++)
#pragma unroll
        for (int j = 0; j < 4; j++)
#pragma unroll
            for (int e = 0; e < 4; e++) acc[i][j][e] = 0.f;

    // prologue: stages 0,1
#pragma unroll
    for (int p = 0; p < 2; p++) {
        const uint32_t bo = sS + (uint32_t)p * GSTG;
        const int ko = p * BKK;
#pragma unroll
        for (int i = 0; i < 4; i++) {
            CP_ASYNC16(bo + ds[i], ag[i] + ko);
            CP_ASYNC16(bo + STGB + ds[i], bg[i] + ko);
        }
        CP_COMMIT();
    }

    const uint32_t aoff = (uint32_t)((wm + (lane & 15)) * GSTR + ((lane >> 4) << 3)) * 2;
    const uint32_t boff = STGB + (uint32_t)((wn + ((lane >> 4) << 3) + (lane & 7)) * GSTR
                                            + (((lane >> 3) & 1) << 3)) * 2;

    int buf = 0, nbuf = 2;
    for (int it = 0; it < NITER; it++) {
        if (it + 1 < NITER) { CP_WAIT(1); } else { CP_WAIT(0); }
        __syncthreads();
        if (it + 2 < NITER) {
            const uint32_t bo = sS + (uint32_t)nbuf * GSTG;
            const int ko = (it + 2) * BKK;
#pragma unroll
            for (int i = 0; i < 4; i++) {
                CP_ASYNC16(bo + ds[i], ag[i] + ko);
                CP_ASYNC16(bo + STGB + ds[i], bg[i] + ko);
            }
            CP_COMMIT();
            nbuf = (nbuf == 2) ? 0 : nbuf + 1;
        }

        const uint32_t base = sS + (uint32_t)buf * GSTG;
        buf = (buf == 2) ? 0 : buf + 1;
#pragma unroll
        for (int kh = 0; kh < 4; kh++) {           // 4 x k16 per BK=64
            uint32_t a[4][4], bfr[4][2];
#pragma unroll
            for (int mi = 0; mi < 4; mi++) {
                uint32_t addr = base + aoff + (uint32_t)(mi * 16 * GSTR + kh * 16) * 2;
                ldmx4(addr, a[mi][0], a[mi][1], a[mi][2], a[mi][3]);
            }
#pragma unroll
            for (int j = 0; j < 2; j++) {
                uint32_t addr = base + boff + (uint32_t)(j * 16 * GSTR + kh * 16) * 2;
                uint32_t r0, r1, r2, r3;
                ldmx4(addr, r0, r1, r2, r3);
                bfr[j*2][0] = r0; bfr[j*2][1] = r1;
                bfr[j*2+1][0] = r2; bfr[j*2+1][1] = r3;
            }
#pragma unroll
            for (int mi = 0; mi < 4; mi++)
#pragma unroll
                for (int ni = 0; ni < 4; ni++)
                    mma_bf16(acc[mi][ni], a[mi][0], a[mi][1], a[mi][2], a[mi][3],
                             bfr[ni][0], bfr[ni][1]);
        }
    }

    // epilogue
    const int r0 = bm + wm + (lane >> 2);
#pragma unroll
    for (int mi = 0; mi < 4; mi++) {
#pragma unroll
        for (int ni = 0; ni < 4; ni++) {
            const int row = r0 + mi * 16;
            if constexpr (MODE == 0) {
                __nv_bfloat16* Cb = (__nv_bfloat16*)Cv
                    + (size_t)(bn >> 10) * MROWS * DMODEL;
                const int col = (bn & 1023) + wn + (lane & 3) * 2 + ni * 8;
                *(__nv_bfloat162*)(Cb + (size_t)row * DMODEL + col) =
                    __floats2bfloat162_rn(acc[mi][ni][0], acc[mi][ni][1]);
                *(__nv_bfloat162*)(Cb + (size_t)(row + 8) * DMODEL + col) =
                    __floats2bfloat162_rn(acc[mi][ni][2], acc[mi][ni][3]);
            } else {
                float* Cf = (float*)Cv;
                const int col = bn + wn + (lane & 3) * 2 + ni * 8;
                float2 v0 = make_float2(acc[mi][ni][0], acc[mi][ni][1]);
                float2 v1 = make_float2(acc[mi][ni][2], acc[mi][ni][3]);
                const float2 bb = *(const float2*)(bias + col);
                const float2 x0 = *(const float2*)(resid + (size_t)row * DMODEL + col);
                const float2 x1 = *(const float2*)(resid + (size_t)(row + 8) * DMODEL + col);
                v0.x += bb.x + x0.x; v0.y += bb.y + x0.y;
                v1.x += bb.x + x1.x; v1.y += bb.y + x1.y;
                *(float2*)(Cf + (size_t)row * DMODEL + col)       = v0;
                *(float2*)(Cf + (size_t)(row + 8) * DMODEL + col) = v1;
            }
        }
    }
}

// ---------------------------------------------------------------------------
// Flash attention on mma.sync (bf16 in/out, fp32 accum), fixed-max softmax.
// 128 threads, 4 warps, 2 slabs/warp. ATKV=128 with 2-stage ring: 16 KV
// iterations (half the barrier count); each iteration processes two 64-key
// sub-blocks with the proven body. Pipeline: wait(0) -> sync -> prefetch
// next stage -> compute (load overlaps the 2x compute block).
// smem 92.2KB -> 2 CTAs/SM (same occupancy as before; isolates barriers).
// ---------------------------------------------------------------------------
#define ATQ   128
#define ATKV  128
#define ASTR  72
#define AQBYTES  (ATQ * ASTR * 2)          // 18432
#define AKVB     (ATKV * ASTR * 2)         // 18432 (per tensor per stage)
#define ASTGB    (2 * AKVB)                // 36864 (K + V per stage)
#define ASMEM    (AQBYTES + 2 * ASTGB)     // 92160
#define CEXP  0.180336880f                 // 0.125 * log2(e)
#define NKV   (SEQ / ATKV)                 // 16
#define SUBB  (64 * ASTR * 2)              // 64-row sub-block byte offset

__global__ __launch_bounds__(128)
void attn_mma(const __nv_bfloat16* __restrict__ Q, const __nv_bfloat16* __restrict__ K,
              const __nv_bfloat16* __restrict__ V, __nv_bfloat16* __restrict__ O)
{
    extern __shared__ char smattn[];
    const uint32_t sQ = smem_u32(smattn);
    const uint32_t sKV = sQ + AQBYTES;     // stage s: K at s*ASTGB, V at +AKVB

    const int t = threadIdx.x, lane = t & 31, warp = t >> 5;   // warp 0..3
    const int b = blockIdx.z, h = blockIdx.y;
    const int q0 = blockIdx.x * ATQ;
    const size_t base = (size_t)b * SEQ * DMODEL + (size_t)h * HDIM;

    // prologue: Q (1 group), KV stage 0 (1 group). 128 threads.
#pragma unroll
    for (int i = 0; i < 8; i++) {
        int idx = t + i * 128, row = idx >> 3, ch = idx & 7;
        CP_ASYNC16(sQ + (uint32_t)(row * ASTR + ch * 8) * 2,
                   Q + base + (size_t)(q0 + row) * DMODEL + ch * 8);
    }
    CP_COMMIT();
    {
        const uint32_t bo = sKV;
#pragma unroll
        for (int i = 0; i < 8; i++) {
            int idx = t + i * 128, row = idx >> 3, ch = idx & 7;   // 128 rows
            CP_ASYNC16(bo + (uint32_t)(row * ASTR + ch * 8) * 2,
                       K + base + (size_t)row * DMODEL + ch * 8);
            CP_ASYNC16(bo + AKVB + (uint32_t)(row * ASTR + ch * 8) * 2,
                       V + base + (size_t)row * DMODEL + ch * 8);
        }
        CP_COMMIT();
    }

    CP_WAIT(1);            // Q done (stage-0 KV may be pending)
    __syncthreads();

    // Q fragments for both slabs, resident for the whole KV loop
    uint32_t qa0[4][4], qa1[4][4];
    {
        const uint32_t aq0 = (uint32_t)((warp * 32 + (lane & 15)) * ASTR + ((lane >> 4) << 3));
        const uint32_t aq1 = (uint32_t)((warp * 32 + 16 + (lane & 15)) * ASTR + ((lane >> 4) << 3));
#pragma unroll
        for (int kh = 0; kh < 4; kh++) {
            ldmx4(sQ + (aq0 + kh * 16) * 2, qa0[kh][0], qa0[kh][1], qa0[kh][2], qa0[kh][3]);
            ldmx4(sQ + (aq1 + kh * 16) * 2, qa1[kh][0], qa1[kh][1], qa1[kh][2], qa1[kh][3]);
        }
    }

    float oacc0[8][4], oacc1[8][4];
#pragma unroll
    for (int j = 0; j < 8; j++)
#pragma unroll
        for (int e = 0; e < 4; e++) { oacc0[j][e] = 0.f; oacc1[j][e] = 0.f; }
    float l0a = 0.f, l0b = 0.f, l1a = 0.f, l1b = 0.f;

    const uint32_t koff = (uint32_t)((((lane >> 4) << 3) + (lane & 7)) * ASTR
                                     + (((lane >> 3) & 1) << 3));
    const uint32_t voff = (uint32_t)((lane & 15) * ASTR + ((lane >> 4) << 3));

    for (int it = 0; it < NKV; it++) {
        CP_WAIT(0);        // stage `it` resident
        __syncthreads();   // all warps done reading the other buffer
        if (it + 1 < NKV) {
            const uint32_t bo = sKV + (uint32_t)((it + 1) & 1) * ASTGB;
            const size_t kvb = base + (size_t)((it + 1) * ATKV) * DMODEL;
#pragma unroll
            for (int i = 0; i < 8; i++) {
                int idx = t + i * 128, row = idx >> 3, ch = idx & 7;
                CP_ASYNC16(bo + (uint32_t)(row * ASTR + ch * 8) * 2,
                           K + kvb + (size_t)row * DMODEL + ch * 8);
                CP_ASYNC16(bo + AKVB + (uint32_t)(row * ASTR + ch * 8) * 2,
                           V + kvb + (size_t)row * DMODEL + ch * 8);
            }
            CP_COMMIT();
        }

        const uint32_t kbs = sKV + (uint32_t)(it & 1) * ASTGB;
        const uint32_t vbs = kbs + AKVB;

        // two 64-key sub-blocks per stage
#pragma unroll
        for (int sb = 0; sb < 2; sb++) {
            const uint32_t kb = kbs + (uint32_t)sb * SUBB;
            const uint32_t vb = vbs + (uint32_t)sb * SUBB;

            uint32_t pa0[4][4], pa1[4][4];
            // S = Q @ K^T in two n-halves (keys [0,32) then [32,64))
#pragma unroll
            for (int half = 0; half < 2; half++) {
                float s0[4][4], s1[4][4];
#pragma unroll
                for (int j = 0; j < 4; j++)
#pragma unroll
                    for (int e = 0; e < 4; e++) { s0[j][e] = 0.f; s1[j][e] = 0.f; }
#pragma unroll
                for (int kh = 0; kh < 4; kh++) {
#pragma unroll
                    for (int j2l = 0; j2l < 2; j2l++) {
                        const int j2 = half * 2 + j2l;
                        uint32_t r0, r1, r2, r3;
                        ldmx4(kb + (koff + (uint32_t)(j2 * 16 * ASTR + kh * 16)) * 2,
                              r0, r1, r2, r3);
                        mma_bf16(s0[j2l*2],   qa0[kh][0], qa0[kh][1], qa0[kh][2], qa0[kh][3], r0, r1);
                        mma_bf16(s0[j2l*2+1], qa0[kh][0], qa0[kh][1], qa0[kh][2], qa0[kh][3], r2, r3);
                        mma_bf16(s1[j2l*2],   qa1[kh][0], qa1[kh][1], qa1[kh][2], qa1[kh][3], r0, r1);
                        mma_bf16(s1[j2l*2+1], qa1[kh][0], qa1[kh][1], qa1[kh][2], qa1[kh][3], r2, r3);
                    }
                }
                // fixed-max softmax: p = 2^(s*CEXP)
#pragma unroll
                for (int j2l = 0; j2l < 2; j2l++) {
#pragma unroll
                    for (int u = 0; u < 2; u++) {
                        const int j = j2l * 2 + u;
                        float p00 = ex2(s0[j][0] * CEXP);
                        float p01 = ex2(s0[j][1] * CEXP);
                        float p02 = ex2(s0[j][2] * CEXP);
                        float p03 = ex2(s0[j][3] * CEXP);
                        l0a += p00 + p01; l0b += p02 + p03;
                        pa0[half*2 + j2l][u*2]     = pack_bf16(p00, p01);
                        pa0[half*2 + j2l][u*2 + 1] = pack_bf16(p02, p03);
                        float p10 = ex2(s1[j][0] * CEXP);
                        float p11 = ex2(s1[j][1] * CEXP);
                        float p12 = ex2(s1[j][2] * CEXP);
                        float p13 = ex2(s1[j][3] * CEXP);
                        l1a += p10 + p11; l1b += p12 + p13;
                        pa1[half*2 + j2l][u*2]     = pack_bf16(p10, p11);
                        pa1[half*2 + j2l][u*2 + 1] = pack_bf16(p12, p13);
                    }
                }
            }

            // O += P @ V (un-normalized); each V fragment feeds both slabs
#pragma unroll
            for (int kk = 0; kk < 4; kk++) {
#pragma unroll
                for (int j2 = 0; j2 < 4; j2++) {
                    uint32_t r0, r1, r2, r3;
                    ldmx4t(vb + (voff + (uint32_t)(kk * 16 * ASTR + j2 * 16)) * 2,
                           r0, r1, r2, r3);
                    mma_bf16(oacc0[j2*2],   pa0[kk][0], pa0[kk][1], pa0[kk][2], pa0[kk][3], r0, r1);
                    mma_bf16(oacc0[j2*2+1], pa0[kk][0], pa0[kk][1], pa0[kk][2], pa0[kk][3], r2, r3);
                    mma_bf16(oacc1[j2*2],   pa1[kk][0], pa1[kk][1], pa1[kk][2], pa1[kk][3], r0, r1);
                    mma_bf16(oacc1[j2*2+1], pa1[kk][0], pa1[kk][1], pa1[kk][2], pa1[kk][3], r2, r3);
                }
            }
        }
    }

    l0a += __shfl_xor_sync(0xffffffffu, l0a, 1);
    l0a += __shfl_xor_sync(0xffffffffu, l0a, 2);
    l0b += __shfl_xor_sync(0xffffffffu, l0b, 1);
    l0b += __shfl_xor_sync(0xffffffffu, l0b, 2);
    l1a += __shfl_xor_sync(0xffffffffu, l1a, 1);
    l1a += __shfl_xor_sync(0xffffffffu, l1a, 2);
    l1b += __shfl_xor_sync(0xffffffffu, l1b, 1);
    l1b += __shfl_xor_sync(0xffffffffu, l1b, 2);
    const float i0a = 1.f / l0a, i0b = 1.f / l0b;
    const float i1a = 1.f / l1a, i1b = 1.f / l1b;

    const int r0r = warp * 32 + (lane >> 2);
    __nv_bfloat16* o0 = O + (size_t)(b * SEQ + q0 + r0r) * DMODEL + h * HDIM + (lane & 3) * 2;
    __nv_bfloat16* o1 = o0 + (size_t)8 * DMODEL;
    __nv_bfloat16* o2 = o0 + (size_t)16 * DMODEL;
    __nv_bfloat16* o3 = o0 + (size_t)24 * DMODEL;
#pragma unroll
    for (int jn = 0; jn < 8; jn++) {
        *(__nv_bfloat162*)(o0 + jn * 8) =
            __floats2bfloat162_rn(oacc0[jn][0] * i0a, oacc0[jn][1] * i0a);
        *(__nv_bfloat162*)(o1 + jn * 8) =
            __floats2bfloat162_rn(oacc0[jn][2] * i0b, oacc0[jn][3] * i0b);
        *(__nv_bfloat162*)(o2 + jn * 8) =
            __floats2bfloat162_rn(oacc1[jn][0] * i1a, oacc1[jn][1] * i1a);
        *(__nv_bfloat162*)(o3 + jn * 8) =
            __floats2bfloat162_rn(oacc1[jn][2] * i1b, oacc1[jn][3] * i1b);
    }
}

// ---------------------------------------------------------------------------
// fp32 -> bf16 cast (elementwise, vectorized)
// ---------------------------------------------------------------------------
__global__ __launch_bounds__(256)
void cast_bf16(const float* __restrict__ in, __nv_bfloat16* __restrict__ out, int n4)
{
    int i = blockIdx.x * blockDim.x + threadIdx.x;
    if (i >= n4) return;
    float4 v = *(const float4*)(in + (size_t)i * 4);
    *(__nv_bfloat162*)(out + (size_t)i * 4)     = __floats2bfloat162_rn(v.x, v.y);
    *(__nv_bfloat162*)(out + (size_t)i * 4 + 2) = __floats2bfloat162_rn(v.z, v.w);
}

// ---------------------------------------------------------------------------
// Transpose + cast all 4 weights: in[K,N] fp32 -> out[N,K] bf16 (z selects).
// ---------------------------------------------------------------------------
__global__ __launch_bounds__(256)
void transpose_cast4(const float* __restrict__ w0, const float* __restrict__ w1,
                     const float* __restrict__ w2, const float* __restrict__ w3,
                     __nv_bfloat16* __restrict__ oqkv, __nv_bfloat16* __restrict__ op)
{
    const int z = blockIdx.z;
    const float* in  = (z == 0) ? w0 : (z == 1) ? w1 : (z == 2) ? w2 : w3;
    __nv_bfloat16* out = (z < 3) ? (oqkv + (size_t)z * DMODEL * DMODEL) : op;
    __shared__ float tile[32][33];
    const int n0 = blockIdx.x * 32;
    const int k0 = blockIdx.y * 32;
    const int tx = threadIdx.x & 31;
    const int ty = threadIdx.x >> 5;   // 0..7
#pragma unroll
    for (int i = 0; i < 32; i += 8)
        tile[ty + i][tx] = in[(size_t)(k0 + ty + i) * DMODEL + n0 + tx];
    __syncthreads();
#pragma unroll
    for (int i = 0; i < 32; i += 8)
        out[(size_t)(n0 + ty + i) * DMODEL + k0 + tx] = __float2bfloat16(tile[tx][ty + i]);
}

// ---------------------------------------------------------------------------
// LayerNorm: one block per row (1024 elems), 256 threads, eps = 1e-6
// ---------------------------------------------------------------------------
__global__ __launch_bounds__(256)
void ln_kernel(const float* __restrict__ Y, const float* __restrict__ gamma,
               const float* __restrict__ beta, float* __restrict__ out)
{
    const int row = blockIdx.x;
    const int t = threadIdx.x;
    const float* y = Y + (size_t)row * DMODEL;

    float4 v = *(const float4*)(y + t * 4);
    float s  = v.x + v.y + v.z + v.w;
    float ss = v.x*v.x + v.y*v.y + v.z*v.z + v.w*v.w;

    __shared__ float rs[8], rss[8];
    int lane = t & 31, wid = t >> 5;
#pragma unroll
    for (int o = 16; o > 0; o >>= 1) {
        s  += __shfl_xor_sync(0xffffffffu, s,  o);
        ss += __shfl_xor_sync(0xffffffffu, ss, o);
    }
    if (lane == 0) { rs[wid] = s; rss[wid] = ss; }
    __syncthreads();
    if (wid == 0) {
        s  = (lane < 8) ? rs[lane]  : 0.f;
        ss = (lane < 8) ? rss[lane] : 0.f;
#pragma unroll
        for (int o = 4; o > 0; o >>= 1) {
            s  += __shfl_xor_sync(0xffffffffu, s,  o);
            ss += __shfl_xor_sync(0xffffffffu, ss, o);
        }
        if (lane == 0) { rs[0] = s; rss[0] = ss; }
    }
    __syncthreads();

    float mean = rs[0] * (1.f / DMODEL);
    float var  = rss[0] * (1.f / DMODEL) - mean * mean;
    float rstd = rsqrtf(var + 1e-6f);

    float4 g  = *(const float4*)(gamma + t * 4);
    float4 be = *(const float4*)(beta  + t * 4);
    float4 r;
    r.x = (v.x - mean) * rstd * g.x + be.x;
    r.y = (v.y - mean) * rstd * g.y + be.y;
    r.z = (v.z - mean) * rstd * g.z + be.z;
    r.w = (v.w - mean) * rstd * g.w + be.w;
    *(float4*)(out + (size_t)row * DMODEL + t * 4) = r;
}

// ---------------------------------------------------------------------------
// Launch
// ---------------------------------------------------------------------------
extern "C" void kernel_launch(void* const* d_in, const int* in_sizes, int n_in,
                              void* d_out, int out_size)
{
    const float* x      = (const float*)d_in[0];
    const float* w_q    = (const float*)d_in[1];
    const float* w_k    = (const float*)d_in[2];
    const float* w_v    = (const float*)d_in[3];
    const float* w_proj = (const float*)d_in[4];
    const float* b_proj = (const float*)d_in[5];
    const float* gamma  = (const float*)d_in[6];
    const float* beta   = (const float*)d_in[7];
    float* out = (float*)d_out;

    float* y;
    __nv_bfloat16 *xb, *qkvb, *ob, *wqkv, *wpb;
    cudaGetSymbolAddress((void**)&y,    g_y);
    cudaGetSymbolAddress((void**)&xb,   g_xb);
    cudaGetSymbolAddress((void**)&qkvb, g_qkvb);
    cudaGetSymbolAddress((void**)&ob,   g_ob);
    cudaGetSymbolAddress((void**)&wqkv, g_wqkv);
    cudaGetSymbolAddress((void**)&wpb,  g_wpb);

    cudaFuncSetAttribute(gemm_mma<0>, cudaFuncAttributeMaxDynamicSharedMemorySize, GSMEM);
    cudaFuncSetAttribute(gemm_mma<1>, cudaFuncAttributeMaxDynamicSharedMemorySize, GSMEM);
    cudaFuncSetAttribute(attn_mma, cudaFuncAttributeMaxDynamicSharedMemorySize, ASMEM);

    // Casts / weight transposes
    const int n4 = MROWS * DMODEL / 4;
    cast_bf16<<<(n4 + 255) / 256, 256>>>(x, xb, n4);
    dim3 tg(DMODEL / 32, DMODEL / 32, 4);
    transpose_cast4<<<tg, 256>>>(w_q, w_k, w_v, w_proj, wqkv, wpb);

    // Fused QKV projection (bf16 out, split into q/k/v regions)
    dim3 gq(3 * DMODEL / BN, MROWS / BM);   // (24, 64)
    gemm_mma<0><<<gq, 256, GSMEM>>>(xb, wqkv, qkvb, nullptr, nullptr);

    // Flash attention on tensor cores (ATKV=128, 2-stage, 16 barriers)
    dim3 ga(SEQ / ATQ, NHEAD, BATCH);       // (16, 16, 4)
    attn_mma<<<ga, 128, ASMEM>>>(qkvb, qkvb + (size_t)MROWS * DMODEL,
                                 qkvb + (size_t)2 * MROWS * DMODEL, ob);

    // proj + bias + residual (fp32 out)
    dim3 gp(DMODEL / BN, MROWS / BM);       // (8, 64)
    gemm_mma<1><<<gp, 256, GSMEM>>>(ob, wpb, y, b_proj, x);

    ln_kernel<<<MROWS, 256>>>(y, gamma, beta, out);
}